// round 1
// baseline (speedup 1.0000x reference)
#include <cuda_runtime.h>
#include <cuda_bf16.h>
#include <cstddef>

#define N_NODES 50000
#define N_EDGES 500000
#define IN_C 512
#define HID_C 256
#define OUT_C 128

#define SCAN_B 1024
#define NB ((N_NODES + SCAN_B - 1) / SCAN_B)   // 49

// ---------------- scratch (device globals; no allocation) ----------------
__device__ int   g_degi[N_NODES];
__device__ int   g_cnt[N_NODES];
__device__ int   g_off[N_NODES + 1];
__device__ int   g_bsum[NB];
__device__ int   g_csr_src[N_EDGES];
__device__ float g_csr_w[N_EDGES];
__device__ float g_dis[N_NODES];
__device__ float g_selfn[N_NODES];
__device__ float g_h1[(size_t)N_NODES * HID_C];
__device__ float g_h [(size_t)N_NODES * HID_C];
__device__ float g_g [(size_t)N_NODES * HID_C];
__device__ float g_wcat[HID_C * 2 * OUT_C];   // [256][256] = [w_mu | w_ls]
__device__ float g_bcat[2 * OUT_C];

// ---------------- CSR build ----------------
__global__ void k_zero() {
    int i = blockIdx.x * blockDim.x + threadIdx.x;
    if (i < N_NODES) { g_degi[i] = 0; g_cnt[i] = 0; }
}

__global__ void k_count(const int* __restrict__ dst) {
    int e = blockIdx.x * blockDim.x + threadIdx.x;
    if (e < N_EDGES) atomicAdd(&g_degi[dst[e]], 1);
}

__global__ void k_scan1() {
    __shared__ int sh[SCAN_B];
    int tid = threadIdx.x;
    int i = blockIdx.x * SCAN_B + tid;
    int v = (i < N_NODES) ? g_degi[i] : 0;
    sh[tid] = v;
    __syncthreads();
    for (int off = 1; off < SCAN_B; off <<= 1) {
        int t = (tid >= off) ? sh[tid - off] : 0;
        __syncthreads();
        sh[tid] += t;
        __syncthreads();
    }
    if (i < N_NODES) g_off[i + 1] = sh[tid];
    if (tid == SCAN_B - 1) g_bsum[blockIdx.x] = sh[tid];
}

__global__ void k_scan2() {
    // single thread: 49 elements
    int run = 0;
    for (int b = 0; b < NB; b++) {
        int t = g_bsum[b];
        g_bsum[b] = run;
        run += t;
    }
    g_off[0] = 0;
}

__global__ void k_scan3() {
    int tid = threadIdx.x;
    int i = blockIdx.x * SCAN_B + tid;
    if (i < N_NODES) g_off[i + 1] += g_bsum[blockIdx.x];
}

__global__ void k_node_norm() {
    int n = blockIdx.x * blockDim.x + threadIdx.x;
    if (n < N_NODES) {
        float degf = (float)g_degi[n] + 1.0f;
        g_dis[n]   = rsqrtf(degf);
        g_selfn[n] = 1.0f / degf;
    }
}

__global__ void k_fill(const int* __restrict__ src, const int* __restrict__ dst) {
    int e = blockIdx.x * blockDim.x + threadIdx.x;
    if (e < N_EDGES) {
        int d = dst[e];
        int s = src[e];
        int p = atomicAdd(&g_cnt[d], 1);
        int idx = g_off[d] + p;
        g_csr_src[idx] = s;
        g_csr_w[idx] = g_dis[s];   // dis[dst] factored out per-node in aggregator
    }
}

__global__ void k_concat(const float* __restrict__ w_mu, const float* __restrict__ w_ls,
                         const float* __restrict__ b_mu, const float* __restrict__ b_ls) {
    int i = blockIdx.x * blockDim.x + threadIdx.x;   // over 256*256
    if (i < HID_C * 2 * OUT_C) {
        int k = i / (2 * OUT_C);
        int c = i % (2 * OUT_C);
        g_wcat[i] = (c < OUT_C) ? w_mu[k * OUT_C + c] : w_ls[k * OUT_C + (c - OUT_C)];
    }
    if (i < 2 * OUT_C) {
        g_bcat[i] = (i < OUT_C) ? b_mu[i] : b_ls[i - OUT_C];
    }
}

// ---------------- fp32 SIMT GEMM: C[M,N] = A[M,K] @ B[K,N] (+bias), split epilogue ----------------
#define BM 128
#define BN 128
#define BK 16
#define TM 8
#define TN 8

__global__ __launch_bounds__(256)
void k_gemm(const float* __restrict__ A, const float* __restrict__ B,
            const float* __restrict__ bias,
            float* __restrict__ out0, float* __restrict__ out1,
            int M, int K, int N, int split)
{
    __shared__ float As[BK][BM];
    __shared__ float Bs[BK][BN];

    int tid = threadIdx.x;
    int row0 = blockIdx.y * BM;
    int col0 = blockIdx.x * BN;

    int tx = tid % 16;        // col group
    int ty = tid / 16;        // row group

    float acc[TM][TN];
    #pragma unroll
    for (int i = 0; i < TM; i++)
        #pragma unroll
        for (int j = 0; j < TN; j++) acc[i][j] = 0.0f;

    int a_r = tid >> 2;             // 0..63
    int a_c = (tid & 3) * 4;        // 0,4,8,12
    int b_r = tid >> 5;             // 0..7
    int b_c = (tid & 31) * 4;       // 0..124

    for (int k0 = 0; k0 < K; k0 += BK) {
        #pragma unroll
        for (int p = 0; p < 2; p++) {
            int r = a_r + p * 64;
            int gr = row0 + r;
            float4 v = make_float4(0.f, 0.f, 0.f, 0.f);
            if (gr < M) v = *(const float4*)&A[(size_t)gr * K + k0 + a_c];
            As[a_c + 0][r] = v.x;
            As[a_c + 1][r] = v.y;
            As[a_c + 2][r] = v.z;
            As[a_c + 3][r] = v.w;
        }
        #pragma unroll
        for (int p = 0; p < 2; p++) {
            int r = b_r + p * 8;
            *(float4*)&Bs[r][b_c] = *(const float4*)&B[(size_t)(k0 + r) * N + col0 + b_c];
        }
        __syncthreads();

        #pragma unroll
        for (int kk = 0; kk < BK; kk++) {
            float af[TM], bf[TN];
            *(float4*)&af[0] = *(const float4*)&As[kk][ty * TM];
            *(float4*)&af[4] = *(const float4*)&As[kk][ty * TM + 4];
            *(float4*)&bf[0] = *(const float4*)&Bs[kk][tx * TN];
            *(float4*)&bf[4] = *(const float4*)&Bs[kk][tx * TN + 4];
            #pragma unroll
            for (int i = 0; i < TM; i++)
                #pragma unroll
                for (int j = 0; j < TN; j++)
                    acc[i][j] = fmaf(af[i], bf[j], acc[i][j]);
        }
        __syncthreads();
    }

    #pragma unroll
    for (int i = 0; i < TM; i++) {
        int r = row0 + ty * TM + i;
        if (r >= M) continue;
        #pragma unroll
        for (int j = 0; j < TN; j++) {
            int c = col0 + tx * TN + j;
            float v = acc[i][j] + (bias ? bias[c] : 0.0f);
            if (c < split) out0[(size_t)r * split + c] = v;
            else           out1[(size_t)r * split + (c - split)] = v;
        }
    }
}

// ---------------- CSR aggregation: out[n] = dis[n]*sum_e w_e*h[src_e] + selfn[n]*h[n] + b ----------------
__global__ void k_aggregate(const float* __restrict__ hin,
                            const float* __restrict__ bias,
                            float* __restrict__ hout,
                            int do_relu)
{
    int n = blockIdx.x;
    int t = threadIdx.x;            // 0..63, each owns 4 features
    int fo = t * 4;

    float4 acc = make_float4(0.f, 0.f, 0.f, 0.f);
    int beg = g_off[n], end = g_off[n + 1];
    for (int i = beg; i < end; i++) {
        int   s = g_csr_src[i];
        float w = g_csr_w[i];
        float4 v = *(const float4*)&hin[(size_t)s * HID_C + fo];
        acc.x = fmaf(w, v.x, acc.x);
        acc.y = fmaf(w, v.y, acc.y);
        acc.z = fmaf(w, v.z, acc.z);
        acc.w = fmaf(w, v.w, acc.w);
    }
    float dn = g_dis[n];
    float sn = g_selfn[n];
    float4 hv = *(const float4*)&hin[(size_t)n * HID_C + fo];
    float4 r;
    float bx = bias ? bias[fo + 0] : 0.f;
    float by = bias ? bias[fo + 1] : 0.f;
    float bz = bias ? bias[fo + 2] : 0.f;
    float bw = bias ? bias[fo + 3] : 0.f;
    r.x = dn * acc.x + sn * hv.x + bx;
    r.y = dn * acc.y + sn * hv.y + by;
    r.z = dn * acc.z + sn * hv.z + bz;
    r.w = dn * acc.w + sn * hv.w + bw;
    if (do_relu) {
        r.x = fmaxf(r.x, 0.f);
        r.y = fmaxf(r.y, 0.f);
        r.z = fmaxf(r.z, 0.f);
        r.w = fmaxf(r.w, 0.f);
    }
    *(float4*)&hout[(size_t)n * HID_C + fo] = r;
}

// ---------------- launch ----------------
extern "C" void kernel_launch(void* const* d_in, const int* in_sizes, int n_in,
                              void* d_out, int out_size)
{
    const float* x    = (const float*)d_in[0];
    const int*   ei   = (const int*)  d_in[1];
    const float* w1   = (const float*)d_in[2];
    const float* b1   = (const float*)d_in[3];
    const float* w_mu = (const float*)d_in[4];
    const float* b_mu = (const float*)d_in[5];
    const float* w_ls = (const float*)d_in[6];
    const float* b_ls = (const float*)d_in[7];
    float* out = (float*)d_out;

    const int* src = ei;
    const int* dst = ei + N_EDGES;

    void *p_h1, *p_h, *p_g, *p_wcat, *p_bcat;
    cudaGetSymbolAddress(&p_h1,   g_h1);
    cudaGetSymbolAddress(&p_h,    g_h);
    cudaGetSymbolAddress(&p_g,    g_g);
    cudaGetSymbolAddress(&p_wcat, g_wcat);
    cudaGetSymbolAddress(&p_bcat, g_bcat);
    float* h1   = (float*)p_h1;
    float* h    = (float*)p_h;
    float* g    = (float*)p_g;
    float* wcat = (float*)p_wcat;
    float* bcat = (float*)p_bcat;

    // CSR build
    k_zero<<<(N_NODES + 255) / 256, 256>>>();
    k_count<<<(N_EDGES + 255) / 256, 256>>>(dst);
    k_scan1<<<NB, SCAN_B>>>();
    k_scan2<<<1, 1>>>();
    k_scan3<<<NB, SCAN_B>>>();
    k_node_norm<<<(N_NODES + 255) / 256, 256>>>();
    k_fill<<<(N_EDGES + 255) / 256, 256>>>(src, dst);
    k_concat<<<(HID_C * 2 * OUT_C + 255) / 256, 256>>>(w_mu, w_ls, b_mu, b_ls);

    // h1 = x @ w1
    {
        dim3 grid(HID_C / BN, (N_NODES + BM - 1) / BM);
        k_gemm<<<grid, 256>>>(x, w1, nullptr, h1, h1, N_NODES, IN_C, HID_C, HID_C);
    }

    // h = relu(Â h1 + b1)
    k_aggregate<<<N_NODES, 64>>>(h1, b1, h, 1);

    // g = Â h
    k_aggregate<<<N_NODES, 64>>>(h, nullptr, g, 0);

    // [mu | logstd] = g @ [w_mu|w_ls] + [b_mu|b_ls], split-write into the two output halves
    {
        dim3 grid((2 * OUT_C) / BN, (N_NODES + BM - 1) / BM);
        k_gemm<<<grid, 256>>>(g, wcat, bcat, out, out + (size_t)N_NODES * OUT_C,
                              N_NODES, HID_C, 2 * OUT_C, OUT_C);
    }
}

// round 2
// speedup vs baseline: 1.8085x; 1.8085x over previous
#include <cuda_runtime.h>
#include <cuda_bf16.h>
#include <cstdint>
#include <cstddef>

#define N_NODES 50000
#define N_EDGES 500000
#define IN_C 512
#define HID_C 256
#define OUT_C 128

#define SCAN_B 1024
#define NB ((N_NODES + SCAN_B - 1) / SCAN_B)   // 49

// ---------------- scratch (device globals; no allocation) ----------------
__device__ int   g_degi[N_NODES];
__device__ int   g_cnt[N_NODES];
__device__ int   g_off[N_NODES + 1];
__device__ int   g_bsum[NB];
__device__ int   g_csr_src[N_EDGES];
__device__ float g_csr_w[N_EDGES];
__device__ float g_dis[N_NODES];
__device__ float g_selfn[N_NODES];
__device__ float g_h1[(size_t)N_NODES * HID_C];
__device__ float g_h [(size_t)N_NODES * HID_C];
__device__ float g_g [(size_t)N_NODES * HID_C];
__device__ float g_wcat[HID_C * 2 * OUT_C];   // [256][256] = [w_mu | w_ls]
__device__ float g_bcat[2 * OUT_C];

// ---------------- CSR build ----------------
__global__ void k_zero() {
    int i = blockIdx.x * blockDim.x + threadIdx.x;
    if (i < N_NODES) { g_degi[i] = 0; g_cnt[i] = 0; }
}

__global__ void k_count(const int* __restrict__ dst) {
    int e = blockIdx.x * blockDim.x + threadIdx.x;
    if (e < N_EDGES) atomicAdd(&g_degi[dst[e]], 1);
}

__global__ void k_scan1() {
    __shared__ int sh[SCAN_B];
    int tid = threadIdx.x;
    int i = blockIdx.x * SCAN_B + tid;
    int v = (i < N_NODES) ? g_degi[i] : 0;
    sh[tid] = v;
    __syncthreads();
    for (int off = 1; off < SCAN_B; off <<= 1) {
        int t = (tid >= off) ? sh[tid - off] : 0;
        __syncthreads();
        sh[tid] += t;
        __syncthreads();
    }
    if (i < N_NODES) g_off[i + 1] = sh[tid];
    if (tid == SCAN_B - 1) g_bsum[blockIdx.x] = sh[tid];
}

__global__ void k_scan2() {
    // one warp, 2 elements/lane inclusive->exclusive scan over NB=49
    int lane = threadIdx.x;
    int v0 = (lane < NB) ? g_bsum[lane] : 0;
    int v1 = (lane + 32 < NB) ? g_bsum[lane + 32] : 0;
    int s0 = v0;
    #pragma unroll
    for (int o = 1; o < 32; o <<= 1) {
        int t = __shfl_up_sync(0xffffffffu, s0, o);
        if (lane >= o) s0 += t;
    }
    int tot0 = __shfl_sync(0xffffffffu, s0, 31);
    int s1 = v1;
    #pragma unroll
    for (int o = 1; o < 32; o <<= 1) {
        int t = __shfl_up_sync(0xffffffffu, s1, o);
        if (lane >= o) s1 += t;
    }
    s1 += tot0;
    if (lane < NB)      g_bsum[lane]      = s0 - v0;   // exclusive
    if (lane + 32 < NB) g_bsum[lane + 32] = s1 - v1;
    if (lane == 0) g_off[0] = 0;
}

__global__ void k_scan3() {
    int tid = threadIdx.x;
    int i = blockIdx.x * SCAN_B + tid;
    if (i < N_NODES) g_off[i + 1] += g_bsum[blockIdx.x];
}

__global__ void k_node_norm() {
    int n = blockIdx.x * blockDim.x + threadIdx.x;
    if (n < N_NODES) {
        float degf = (float)g_degi[n] + 1.0f;
        g_dis[n]   = rsqrtf(degf);
        g_selfn[n] = 1.0f / degf;
    }
}

__global__ void k_fill(const int* __restrict__ src, const int* __restrict__ dst) {
    int e = blockIdx.x * blockDim.x + threadIdx.x;
    if (e < N_EDGES) {
        int d = dst[e];
        int s = src[e];
        int p = atomicAdd(&g_cnt[d], 1);
        int idx = g_off[d] + p;
        g_csr_src[idx] = s;
        g_csr_w[idx] = g_dis[s];   // dis[dst] factored out per-node in aggregator
    }
}

__global__ void k_concat(const float* __restrict__ w_mu, const float* __restrict__ w_ls,
                         const float* __restrict__ b_mu, const float* __restrict__ b_ls) {
    int i = blockIdx.x * blockDim.x + threadIdx.x;   // over 256*256
    if (i < HID_C * 2 * OUT_C) {
        int k = i / (2 * OUT_C);
        int c = i % (2 * OUT_C);
        g_wcat[i] = (c < OUT_C) ? w_mu[k * OUT_C + c] : w_ls[k * OUT_C + (c - OUT_C)];
    }
    if (i < 2 * OUT_C) {
        g_bcat[i] = (i < OUT_C) ? b_mu[i] : b_ls[i - OUT_C];
    }
}

// ---------------- TF32 tensor-core GEMM: C[M,N] = A[M,K] @ B[K,N] (+bias) ----------------
// BM=128 BN=128 BK=16, 256 threads = 8 warps, warp tile 32x64 (2x8 m16n8k8 frags)
#define BM 128
#define BN 128
#define BK 16
#define APAD 4
#define BPAD 4

__device__ __forceinline__ uint32_t f2tf32(float v) {
    uint32_t r;
    asm volatile("cvt.rna.tf32.f32 %0, %1;" : "=r"(r) : "f"(v));
    return r;
}

__global__ __launch_bounds__(256)
void k_gemm_tf32(const float* __restrict__ A, const float* __restrict__ B,
                 const float* __restrict__ bias,
                 float* __restrict__ out0, float* __restrict__ out1,
                 int M, int K, int N, int split)
{
    __shared__ uint32_t As[BK][BM + APAD];
    __shared__ uint32_t Bs[BK][BN + BPAD];

    const int tid  = threadIdx.x;
    const int lane = tid & 31;
    const int wid  = tid >> 5;
    const int lrow = lane >> 2;   // 0..7
    const int lcol = lane & 3;    // 0..3

    const int row0 = blockIdx.y * BM;
    const int col0 = blockIdx.x * BN;

    const int wm0 = (wid & 3) * 32;   // warp m offset in tile
    const int wn0 = (wid >> 2) * 64;  // warp n offset in tile

    float acc[2][8][4];
    #pragma unroll
    for (int mi = 0; mi < 2; mi++)
        #pragma unroll
        for (int ni = 0; ni < 8; ni++)
            #pragma unroll
            for (int q = 0; q < 4; q++) acc[mi][ni][q] = 0.0f;

    for (int k0 = 0; k0 < K; k0 += BK) {
        // ---- load A tile (128x16) ----
        #pragma unroll
        for (int p = 0; p < 2; p++) {
            int v = tid + p * 256;        // 0..511
            int r = v >> 2;               // row in tile 0..127
            int c = (v & 3) * 4;          // col 0,4,8,12
            int gr = row0 + r;
            float4 f = make_float4(0.f, 0.f, 0.f, 0.f);
            if (gr < M) f = *(const float4*)&A[(size_t)gr * K + k0 + c];
            As[c + 0][r] = f2tf32(f.x);
            As[c + 1][r] = f2tf32(f.y);
            As[c + 2][r] = f2tf32(f.z);
            As[c + 3][r] = f2tf32(f.w);
        }
        // ---- load B tile (16x128) ----
        #pragma unroll
        for (int p = 0; p < 2; p++) {
            int v = tid + p * 256;        // 0..511
            int r = v >> 5;               // row 0..15
            int c = (v & 31) * 4;         // col 0..124
            float4 f = *(const float4*)&B[(size_t)(k0 + r) * N + col0 + c];
            uint4 u;
            u.x = f2tf32(f.x); u.y = f2tf32(f.y); u.z = f2tf32(f.z); u.w = f2tf32(f.w);
            *(uint4*)&Bs[r][c] = u;
        }
        __syncthreads();

        #pragma unroll
        for (int ks = 0; ks < BK; ks += 8) {
            uint32_t a[2][4];
            #pragma unroll
            for (int mi = 0; mi < 2; mi++) {
                int mr = wm0 + mi * 16 + lrow;
                a[mi][0] = As[ks + lcol    ][mr];
                a[mi][1] = As[ks + lcol    ][mr + 8];
                a[mi][2] = As[ks + 4 + lcol][mr];
                a[mi][3] = As[ks + 4 + lcol][mr + 8];
            }
            #pragma unroll
            for (int ni = 0; ni < 8; ni++) {
                int nc = wn0 + ni * 8 + lrow;
                uint32_t b0 = Bs[ks + lcol    ][nc];
                uint32_t b1 = Bs[ks + 4 + lcol][nc];
                #pragma unroll
                for (int mi = 0; mi < 2; mi++) {
                    asm volatile(
                        "mma.sync.aligned.m16n8k8.row.col.f32.tf32.tf32.f32 "
                        "{%0,%1,%2,%3}, {%4,%5,%6,%7}, {%8,%9}, {%0,%1,%2,%3};\n"
                        : "+f"(acc[mi][ni][0]), "+f"(acc[mi][ni][1]),
                          "+f"(acc[mi][ni][2]), "+f"(acc[mi][ni][3])
                        : "r"(a[mi][0]), "r"(a[mi][1]), "r"(a[mi][2]), "r"(a[mi][3]),
                          "r"(b0), "r"(b1));
                }
            }
        }
        __syncthreads();
    }

    // ---- epilogue: bias + split store ----
    #pragma unroll
    for (int mi = 0; mi < 2; mi++) {
        #pragma unroll
        for (int half = 0; half < 2; half++) {       // c0/c1 then c2/c3 (row, row+8)
            int r = row0 + wm0 + mi * 16 + lrow + half * 8;
            if (r >= M) continue;
            #pragma unroll
            for (int ni = 0; ni < 8; ni++) {
                int c = col0 + wn0 + ni * 8 + lcol * 2;
                float v0 = acc[mi][ni][half * 2 + 0];
                float v1 = acc[mi][ni][half * 2 + 1];
                if (bias) { v0 += bias[c]; v1 += bias[c + 1]; }
                if (c < split) {
                    *(float2*)&out0[(size_t)r * split + c] = make_float2(v0, v1);
                } else {
                    *(float2*)&out1[(size_t)r * split + (c - split)] = make_float2(v0, v1);
                }
            }
        }
    }
}

// ---------------- CSR aggregation: out[n] = dis[n]*sum_e w_e*h[src_e] + selfn[n]*h[n] + b ----------------
__global__ void k_aggregate(const float* __restrict__ hin,
                            const float* __restrict__ bias,
                            float* __restrict__ hout,
                            int do_relu)
{
    int n = blockIdx.x;
    int t = threadIdx.x;            // 0..63, each owns 4 features
    int fo = t * 4;

    float4 acc = make_float4(0.f, 0.f, 0.f, 0.f);
    int beg = g_off[n], end = g_off[n + 1];
    for (int i = beg; i < end; i++) {
        int   s = g_csr_src[i];
        float w = g_csr_w[i];
        float4 v = *(const float4*)&hin[(size_t)s * HID_C + fo];
        acc.x = fmaf(w, v.x, acc.x);
        acc.y = fmaf(w, v.y, acc.y);
        acc.z = fmaf(w, v.z, acc.z);
        acc.w = fmaf(w, v.w, acc.w);
    }
    float dn = g_dis[n];
    float sn = g_selfn[n];
    float4 hv = *(const float4*)&hin[(size_t)n * HID_C + fo];
    float4 r;
    float bx = bias ? bias[fo + 0] : 0.f;
    float by = bias ? bias[fo + 1] : 0.f;
    float bz = bias ? bias[fo + 2] : 0.f;
    float bw = bias ? bias[fo + 3] : 0.f;
    r.x = dn * acc.x + sn * hv.x + bx;
    r.y = dn * acc.y + sn * hv.y + by;
    r.z = dn * acc.z + sn * hv.z + bz;
    r.w = dn * acc.w + sn * hv.w + bw;
    if (do_relu) {
        r.x = fmaxf(r.x, 0.f);
        r.y = fmaxf(r.y, 0.f);
        r.z = fmaxf(r.z, 0.f);
        r.w = fmaxf(r.w, 0.f);
    }
    *(float4*)&hout[(size_t)n * HID_C + fo] = r;
}

// ---------------- launch ----------------
extern "C" void kernel_launch(void* const* d_in, const int* in_sizes, int n_in,
                              void* d_out, int out_size)
{
    const float* x    = (const float*)d_in[0];
    const int*   ei   = (const int*)  d_in[1];
    const float* w1   = (const float*)d_in[2];
    const float* b1   = (const float*)d_in[3];
    const float* w_mu = (const float*)d_in[4];
    const float* b_mu = (const float*)d_in[5];
    const float* w_ls = (const float*)d_in[6];
    const float* b_ls = (const float*)d_in[7];
    float* out = (float*)d_out;

    const int* src = ei;
    const int* dst = ei + N_EDGES;

    void *p_h1, *p_h, *p_g, *p_wcat, *p_bcat;
    cudaGetSymbolAddress(&p_h1,   g_h1);
    cudaGetSymbolAddress(&p_h,    g_h);
    cudaGetSymbolAddress(&p_g,    g_g);
    cudaGetSymbolAddress(&p_wcat, g_wcat);
    cudaGetSymbolAddress(&p_bcat, g_bcat);
    float* h1   = (float*)p_h1;
    float* h    = (float*)p_h;
    float* g    = (float*)p_g;
    float* wcat = (float*)p_wcat;
    float* bcat = (float*)p_bcat;

    // CSR build
    k_zero<<<(N_NODES + 255) / 256, 256>>>();
    k_count<<<(N_EDGES + 255) / 256, 256>>>(dst);
    k_scan1<<<NB, SCAN_B>>>();
    k_scan2<<<1, 32>>>();
    k_scan3<<<NB, SCAN_B>>>();
    k_node_norm<<<(N_NODES + 255) / 256, 256>>>();
    k_fill<<<(N_EDGES + 255) / 256, 256>>>(src, dst);
    k_concat<<<(HID_C * 2 * OUT_C + 255) / 256, 256>>>(w_mu, w_ls, b_mu, b_ls);

    // h1 = x @ w1
    {
        dim3 grid(HID_C / BN, (N_NODES + BM - 1) / BM);
        k_gemm_tf32<<<grid, 256>>>(x, w1, nullptr, h1, h1, N_NODES, IN_C, HID_C, HID_C);
    }

    // h = relu(Â h1 + b1)
    k_aggregate<<<N_NODES, 64>>>(h1, b1, h, 1);

    // g = Â h
    k_aggregate<<<N_NODES, 64>>>(h, nullptr, g, 0);

    // [mu | logstd] = g @ [w_mu|w_ls] + [b_mu|b_ls], split-write into the two output halves
    {
        dim3 grid((2 * OUT_C) / BN, (N_NODES + BM - 1) / BM);
        k_gemm_tf32<<<grid, 256>>>(g, wcat, bcat, out, out + (size_t)N_NODES * OUT_C,
                                   N_NODES, HID_C, 2 * OUT_C, OUT_C);
    }
}

// round 4
// speedup vs baseline: 1.9320x; 1.0683x over previous
#include <cuda_runtime.h>
#include <cuda_bf16.h>
#include <cstdint>
#include <cstddef>

#define N_NODES 50000
#define N_EDGES 500000
#define IN_C 512
#define HID_C 256
#define OUT_C 128

#define SCAN_B 1024
#define NB ((N_NODES + SCAN_B - 1) / SCAN_B)   // 49

// ---------------- scratch (device globals; no allocation) ----------------
__device__ int   g_degi[N_NODES];
__device__ int   g_cnt[N_NODES];
__device__ int   g_off[N_NODES + 1];
__device__ int   g_bsum[NB];
__device__ int2  g_csr[N_EDGES];              // (src, weight-as-bits)
__device__ float g_dis[N_NODES];
__device__ float g_selfn[N_NODES];
__device__ float g_h1[(size_t)N_NODES * HID_C];
__device__ float g_h [(size_t)N_NODES * HID_C];
__device__ float g_g [(size_t)N_NODES * HID_C];
__device__ float g_wcat[HID_C * 2 * OUT_C];   // [256][256] = [w_mu | w_ls]
__device__ float g_bcat[2 * OUT_C];

// ---------------- CSR build ----------------
__global__ void k_zero() {
    int i = blockIdx.x * blockDim.x + threadIdx.x;
    if (i < N_NODES) { g_degi[i] = 0; g_cnt[i] = 0; }
}

__global__ void k_count(const int* __restrict__ dst) {
    int e = blockIdx.x * blockDim.x + threadIdx.x;
    if (e < N_EDGES) atomicAdd(&g_degi[dst[e]], 1);
}

__global__ void k_scan1() {
    __shared__ int sh[SCAN_B];
    int tid = threadIdx.x;
    int i = blockIdx.x * SCAN_B + tid;
    int v = (i < N_NODES) ? g_degi[i] : 0;
    if (i < N_NODES) {                         // fused node-norm (degi is final here)
        float degf = (float)v + 1.0f;
        g_dis[i]   = rsqrtf(degf);
        g_selfn[i] = 1.0f / degf;
    }
    sh[tid] = v;
    __syncthreads();
    for (int off = 1; off < SCAN_B; off <<= 1) {
        int t = (tid >= off) ? sh[tid - off] : 0;
        __syncthreads();
        sh[tid] += t;
        __syncthreads();
    }
    if (i < N_NODES) g_off[i + 1] = sh[tid];
    if (tid == SCAN_B - 1) g_bsum[blockIdx.x] = sh[tid];
}

__global__ void k_scan2() {
    // one warp, 2 elements/lane inclusive->exclusive scan over NB=49
    int lane = threadIdx.x;
    int v0 = (lane < NB) ? g_bsum[lane] : 0;
    int v1 = (lane + 32 < NB) ? g_bsum[lane + 32] : 0;
    int s0 = v0;
    #pragma unroll
    for (int o = 1; o < 32; o <<= 1) {
        int t = __shfl_up_sync(0xffffffffu, s0, o);
        if (lane >= o) s0 += t;
    }
    int tot0 = __shfl_sync(0xffffffffu, s0, 31);
    int s1 = v1;
    #pragma unroll
    for (int o = 1; o < 32; o <<= 1) {
        int t = __shfl_up_sync(0xffffffffu, s1, o);
        if (lane >= o) s1 += t;
    }
    s1 += tot0;
    if (lane < NB)      g_bsum[lane]      = s0 - v0;   // exclusive
    if (lane + 32 < NB) g_bsum[lane + 32] = s1 - v1;
    if (lane == 0) g_off[0] = 0;
}

__global__ void k_scan3() {
    int tid = threadIdx.x;
    int i = blockIdx.x * SCAN_B + tid;
    if (i < N_NODES) g_off[i + 1] += g_bsum[blockIdx.x];
}

__global__ void k_fill(const int* __restrict__ src, const int* __restrict__ dst) {
    int e = blockIdx.x * blockDim.x + threadIdx.x;
    if (e < N_EDGES) {
        int d = dst[e];
        int s = src[e];
        int p = atomicAdd(&g_cnt[d], 1);
        int idx = g_off[d] + p;
        g_csr[idx] = make_int2(s, __float_as_int(g_dis[s]));
    }
}

__global__ void k_concat(const float* __restrict__ w_mu, const float* __restrict__ w_ls,
                         const float* __restrict__ b_mu, const float* __restrict__ b_ls) {
    int i = blockIdx.x * blockDim.x + threadIdx.x;   // over 256*256
    if (i < HID_C * 2 * OUT_C) {
        int k = i / (2 * OUT_C);
        int c = i % (2 * OUT_C);
        g_wcat[i] = (c < OUT_C) ? w_mu[k * OUT_C + c] : w_ls[k * OUT_C + (c - OUT_C)];
    }
    if (i < 2 * OUT_C) {
        g_bcat[i] = (i < OUT_C) ? b_mu[i] : b_ls[i - OUT_C];
    }
}

// ---------------- TF32 tensor-core GEMM, double-buffered ----------------
// BM=128 BN=128 BK=16, 256 threads = 8 warps, warp tile 32x64 (2x8 m16n8k8 frags)
#define BM 128
#define BN 128
#define BK 16
#define APAD 4
#define BPAD 4

__device__ __forceinline__ uint32_t f2tf32(float v) {
    uint32_t r;
    asm volatile("cvt.rna.tf32.f32 %0, %1;" : "=r"(r) : "f"(v));
    return r;
}

__global__ __launch_bounds__(256)
void k_gemm_tf32(const float* __restrict__ A, const float* __restrict__ B,
                 const float* __restrict__ bias,
                 float* __restrict__ out0, float* __restrict__ out1,
                 int M, int K, int N, int split)
{
    __shared__ uint32_t As[2][BK][BM + APAD];
    __shared__ uint32_t Bs[2][BK][BN + BPAD];

    const int tid  = threadIdx.x;
    const int lane = tid & 31;
    const int wid  = tid >> 5;
    const int lrow = lane >> 2;   // 0..7
    const int lcol = lane & 3;    // 0..3

    const int row0 = blockIdx.y * BM;
    const int col0 = blockIdx.x * BN;

    const int wm0 = (wid & 3) * 32;   // warp m offset in tile
    const int wn0 = (wid >> 2) * 64;  // warp n offset in tile

    // per-thread load coordinates (2 float4 for A, 2 float4 for B per tile)
    const int a_r0 = tid >> 2;              // 0..63  (rows tid/4 and +64)
    const int a_c  = (tid & 3) * 4;         // 0,4,8,12
    const int b_r0 = tid >> 5;              // 0..7   (rows tid/32 and +8)
    const int b_c  = (tid & 31) * 4;        // 0..124

    float acc[2][8][4];
    #pragma unroll
    for (int mi = 0; mi < 2; mi++)
        #pragma unroll
        for (int ni = 0; ni < 8; ni++)
            #pragma unroll
            for (int q = 0; q < 4; q++) acc[mi][ni][q] = 0.0f;

    // ---- prologue: load tile 0 into buffer 0 ----
    {
        #pragma unroll
        for (int p = 0; p < 2; p++) {
            int r = a_r0 + p * 64;
            int gr = row0 + r;
            float4 f = make_float4(0.f, 0.f, 0.f, 0.f);
            if (gr < M) f = *(const float4*)&A[(size_t)gr * K + a_c];
            As[0][a_c + 0][r] = f2tf32(f.x);
            As[0][a_c + 1][r] = f2tf32(f.y);
            As[0][a_c + 2][r] = f2tf32(f.z);
            As[0][a_c + 3][r] = f2tf32(f.w);
        }
        #pragma unroll
        for (int p = 0; p < 2; p++) {
            int r = b_r0 + p * 8;
            float4 f = *(const float4*)&B[(size_t)r * N + col0 + b_c];
            uint4 u;
            u.x = f2tf32(f.x); u.y = f2tf32(f.y); u.z = f2tf32(f.z); u.w = f2tf32(f.w);
            *(uint4*)&Bs[0][r][b_c] = u;
        }
    }
    __syncthreads();

    const int nIter = K / BK;
    int buf = 0;

    for (int it = 0; it < nIter; it++) {
        float4 ra[2], rb[2];
        const bool has_next = (it + 1 < nIter);
        if (has_next) {
            int k0 = (it + 1) * BK;
            #pragma unroll
            for (int p = 0; p < 2; p++) {
                int gr = row0 + a_r0 + p * 64;
                ra[p] = make_float4(0.f, 0.f, 0.f, 0.f);
                if (gr < M) ra[p] = *(const float4*)&A[(size_t)gr * K + k0 + a_c];
            }
            #pragma unroll
            for (int p = 0; p < 2; p++) {
                int r = b_r0 + p * 8;
                rb[p] = *(const float4*)&B[(size_t)(k0 + r) * N + col0 + b_c];
            }
        }

        // ---- compute from smem[buf] ----
        #pragma unroll
        for (int ks = 0; ks < BK; ks += 8) {
            uint32_t a[2][4];
            #pragma unroll
            for (int mi = 0; mi < 2; mi++) {
                int mr = wm0 + mi * 16 + lrow;
                a[mi][0] = As[buf][ks + lcol    ][mr];
                a[mi][1] = As[buf][ks + lcol    ][mr + 8];
                a[mi][2] = As[buf][ks + 4 + lcol][mr];
                a[mi][3] = As[buf][ks + 4 + lcol][mr + 8];
            }
            #pragma unroll
            for (int ni = 0; ni < 8; ni++) {
                int nc = wn0 + ni * 8 + lrow;
                uint32_t b0 = Bs[buf][ks + lcol    ][nc];
                uint32_t b1 = Bs[buf][ks + 4 + lcol][nc];
                #pragma unroll
                for (int mi = 0; mi < 2; mi++) {
                    asm volatile(
                        "mma.sync.aligned.m16n8k8.row.col.f32.tf32.tf32.f32 "
                        "{%0,%1,%2,%3}, {%4,%5,%6,%7}, {%8,%9}, {%0,%1,%2,%3};\n"
                        : "+f"(acc[mi][ni][0]), "+f"(acc[mi][ni][1]),
                          "+f"(acc[mi][ni][2]), "+f"(acc[mi][ni][3])
                        : "r"(a[mi][0]), "r"(a[mi][1]), "r"(a[mi][2]), "r"(a[mi][3]),
                          "r"(b0), "r"(b1));
                }
            }
        }

        // ---- stage next tile into the other buffer ----
        if (has_next) {
            int nb = buf ^ 1;
            #pragma unroll
            for (int p = 0; p < 2; p++) {
                int r = a_r0 + p * 64;
                As[nb][a_c + 0][r] = f2tf32(ra[p].x);
                As[nb][a_c + 1][r] = f2tf32(ra[p].y);
                As[nb][a_c + 2][r] = f2tf32(ra[p].z);
                As[nb][a_c + 3][r] = f2tf32(ra[p].w);
            }
            #pragma unroll
            for (int p = 0; p < 2; p++) {
                int r = b_r0 + p * 8;
                uint4 u;
                u.x = f2tf32(rb[p].x); u.y = f2tf32(rb[p].y);
                u.z = f2tf32(rb[p].z); u.w = f2tf32(rb[p].w);
                *(uint4*)&Bs[nb][r][b_c] = u;
            }
        }
        __syncthreads();
        buf ^= 1;
    }

    // ---- epilogue: bias + split store ----
    #pragma unroll
    for (int mi = 0; mi < 2; mi++) {
        #pragma unroll
        for (int half = 0; half < 2; half++) {       // c0/c1 then c2/c3 (row, row+8)
            int r = row0 + wm0 + mi * 16 + lrow + half * 8;
            if (r >= M) continue;
            #pragma unroll
            for (int ni = 0; ni < 8; ni++) {
                int c = col0 + wn0 + ni * 8 + lcol * 2;
                float v0 = acc[mi][ni][half * 2 + 0];
                float v1 = acc[mi][ni][half * 2 + 1];
                if (bias) { v0 += bias[c]; v1 += bias[c + 1]; }
                if (c < split) {
                    *(float2*)&out0[(size_t)r * split + c] = make_float2(v0, v1);
                } else {
                    *(float2*)&out1[(size_t)r * split + (c - split)] = make_float2(v0, v1);
                }
            }
        }
    }
}

// ---------------- CSR aggregation: out[n] = dis[n]*sum_e w_e*h[src_e] + selfn[n]*h[n] + b ----------------
__global__ void k_aggregate(const float* __restrict__ hin,
                            const float* __restrict__ bias,
                            float* __restrict__ hout,
                            int do_relu)
{
    int n = blockIdx.x;
    int t = threadIdx.x;            // 0..63, each owns 4 features
    int fo = t * 4;

    float4 acc = make_float4(0.f, 0.f, 0.f, 0.f);
    int beg = g_off[n], end = g_off[n + 1];

    int i = beg;
    for (; i + 4 <= end; i += 4) {
        int2 e0 = g_csr[i + 0];
        int2 e1 = g_csr[i + 1];
        int2 e2 = g_csr[i + 2];
        int2 e3 = g_csr[i + 3];
        float4 v0 = *(const float4*)&hin[(size_t)e0.x * HID_C + fo];
        float4 v1 = *(const float4*)&hin[(size_t)e1.x * HID_C + fo];
        float4 v2 = *(const float4*)&hin[(size_t)e2.x * HID_C + fo];
        float4 v3 = *(const float4*)&hin[(size_t)e3.x * HID_C + fo];
        float w0 = __int_as_float(e0.y);
        float w1 = __int_as_float(e1.y);
        float w2 = __int_as_float(e2.y);
        float w3 = __int_as_float(e3.y);
        acc.x = fmaf(w0, v0.x, acc.x); acc.y = fmaf(w0, v0.y, acc.y);
        acc.z = fmaf(w0, v0.z, acc.z); acc.w = fmaf(w0, v0.w, acc.w);
        acc.x = fmaf(w1, v1.x, acc.x); acc.y = fmaf(w1, v1.y, acc.y);
        acc.z = fmaf(w1, v1.z, acc.z); acc.w = fmaf(w1, v1.w, acc.w);
        acc.x = fmaf(w2, v2.x, acc.x); acc.y = fmaf(w2, v2.y, acc.y);
        acc.z = fmaf(w2, v2.z, acc.z); acc.w = fmaf(w2, v2.w, acc.w);
        acc.x = fmaf(w3, v3.x, acc.x); acc.y = fmaf(w3, v3.y, acc.y);
        acc.z = fmaf(w3, v3.z, acc.z); acc.w = fmaf(w3, v3.w, acc.w);
    }
    for (; i < end; i++) {
        int2 e = g_csr[i];
        float w = __int_as_float(e.y);
        float4 v = *(const float4*)&hin[(size_t)e.x * HID_C + fo];
        acc.x = fmaf(w, v.x, acc.x);
        acc.y = fmaf(w, v.y, acc.y);
        acc.z = fmaf(w, v.z, acc.z);
        acc.w = fmaf(w, v.w, acc.w);
    }

    float dn = g_dis[n];
    float sn = g_selfn[n];
    float4 hv = *(const float4*)&hin[(size_t)n * HID_C + fo];
    float4 r;
    float bx = bias ? bias[fo + 0] : 0.f;
    float by = bias ? bias[fo + 1] : 0.f;
    float bz = bias ? bias[fo + 2] : 0.f;
    float bw = bias ? bias[fo + 3] : 0.f;
    r.x = dn * acc.x + sn * hv.x + bx;
    r.y = dn * acc.y + sn * hv.y + by;
    r.z = dn * acc.z + sn * hv.z + bz;
    r.w = dn * acc.w + sn * hv.w + bw;
    if (do_relu) {
        r.x = fmaxf(r.x, 0.f);
        r.y = fmaxf(r.y, 0.f);
        r.z = fmaxf(r.z, 0.f);
        r.w = fmaxf(r.w, 0.f);
    }
    *(float4*)&hout[(size_t)n * HID_C + fo] = r;
}

// ---------------- launch ----------------
extern "C" void kernel_launch(void* const* d_in, const int* in_sizes, int n_in,
                              void* d_out, int out_size)
{
    const float* x    = (const float*)d_in[0];
    const int*   ei   = (const int*)  d_in[1];
    const float* w1   = (const float*)d_in[2];
    const float* b1   = (const float*)d_in[3];
    const float* w_mu = (const float*)d_in[4];
    const float* b_mu = (const float*)d_in[5];
    const float* w_ls = (const float*)d_in[6];
    const float* b_ls = (const float*)d_in[7];
    float* out = (float*)d_out;

    const int* src = ei;
    const int* dst = ei + N_EDGES;

    void *p_h1, *p_h, *p_g, *p_wcat, *p_bcat;
    cudaGetSymbolAddress(&p_h1,   g_h1);
    cudaGetSymbolAddress(&p_h,    g_h);
    cudaGetSymbolAddress(&p_g,    g_g);
    cudaGetSymbolAddress(&p_wcat, g_wcat);
    cudaGetSymbolAddress(&p_bcat, g_bcat);
    float* h1   = (float*)p_h1;
    float* h    = (float*)p_h;
    float* g    = (float*)p_g;
    float* wcat = (float*)p_wcat;
    float* bcat = (float*)p_bcat;

    // CSR build
    k_zero<<<(N_NODES + 255) / 256, 256>>>();
    k_count<<<(N_EDGES + 255) / 256, 256>>>(dst);
    k_scan1<<<NB, SCAN_B>>>();
    k_scan2<<<1, 32>>>();
    k_scan3<<<NB, SCAN_B>>>();
    k_fill<<<(N_EDGES + 255) / 256, 256>>>(src, dst);
    k_concat<<<(HID_C * 2 * OUT_C + 255) / 256, 256>>>(w_mu, w_ls, b_mu, b_ls);

    // h1 = x @ w1
    {
        dim3 grid(HID_C / BN, (N_NODES + BM - 1) / BM);
        k_gemm_tf32<<<grid, 256>>>(x, w1, nullptr, h1, h1, N_NODES, IN_C, HID_C, HID_C);
    }

    // h = relu(Â h1 + b1)
    k_aggregate<<<N_NODES, 64>>>(h1, b1, h, 1);

    // g = Â h
    k_aggregate<<<N_NODES, 64>>>(h, nullptr, g, 0);

    // [mu | logstd] = g @ [w_mu|w_ls] + [b_mu|b_ls], split-write into the two output halves
    {
        dim3 grid((2 * OUT_C) / BN, (N_NODES + BM - 1) / BM);
        k_gemm_tf32<<<grid, 256>>>(g, wcat, bcat, out, out + (size_t)N_NODES * OUT_C,
                                   N_NODES, HID_C, 2 * OUT_C, OUT_C);
    }
}

// round 5
// speedup vs baseline: 2.3161x; 1.1988x over previous
#include <cuda_runtime.h>
#include <cuda_bf16.h>
#include <cstdint>
#include <cstddef>

#define N_NODES 50000
#define N_EDGES 500000
#define IN_C 512
#define HID_C 256
#define OUT_C 128

#define SCAN_B 1024
#define NB ((N_NODES + SCAN_B - 1) / SCAN_B)   // 49

// ---------------- scratch (device globals; no allocation) ----------------
__device__ int   g_degi[N_NODES];
__device__ int   g_cnt[N_NODES];
__device__ int   g_off[N_NODES + 1];
__device__ int   g_bsum[NB];
__device__ int2  g_csr[N_EDGES];              // (src, weight-as-bits)
__device__ float g_dis[N_NODES];
__device__ float g_selfn[N_NODES];
__device__ float g_h1[(size_t)N_NODES * HID_C];
__device__ float g_h [(size_t)N_NODES * HID_C];
__device__ float g_g [(size_t)N_NODES * HID_C];

// ---------------- streams/events for capture fork-join (created pre-capture) ----------------
struct Aux {
    cudaStream_t s2;
    cudaEvent_t ev_fork, ev_join;
    Aux() {
        cudaStreamCreateWithFlags(&s2, cudaStreamNonBlocking);
        cudaEventCreateWithFlags(&ev_fork, cudaEventDisableTiming);
        cudaEventCreateWithFlags(&ev_join, cudaEventDisableTiming);
    }
};
static Aux g_aux;

// ---------------- CSR build ----------------
__global__ void k_zero() {
    int i = blockIdx.x * blockDim.x + threadIdx.x;
    if (i < N_NODES) { g_degi[i] = 0; g_cnt[i] = 0; }
}

__global__ void k_count(const int* __restrict__ dst) {
    int e = blockIdx.x * blockDim.x + threadIdx.x;
    if (e < N_EDGES) atomicAdd(&g_degi[dst[e]], 1);
}

__global__ void k_scan1() {
    __shared__ int sh[SCAN_B];
    int tid = threadIdx.x;
    int i = blockIdx.x * SCAN_B + tid;
    int v = (i < N_NODES) ? g_degi[i] : 0;
    if (i < N_NODES) {                         // fused node-norm (degi is final here)
        float degf = (float)v + 1.0f;
        g_dis[i]   = rsqrtf(degf);
        g_selfn[i] = 1.0f / degf;
    }
    sh[tid] = v;
    __syncthreads();
    for (int off = 1; off < SCAN_B; off <<= 1) {
        int t = (tid >= off) ? sh[tid - off] : 0;
        __syncthreads();
        sh[tid] += t;
        __syncthreads();
    }
    if (i < N_NODES) g_off[i + 1] = sh[tid];
    if (tid == SCAN_B - 1) g_bsum[blockIdx.x] = sh[tid];
}

__global__ void k_scan2() {
    int lane = threadIdx.x;
    int v0 = (lane < NB) ? g_bsum[lane] : 0;
    int v1 = (lane + 32 < NB) ? g_bsum[lane + 32] : 0;
    int s0 = v0;
    #pragma unroll
    for (int o = 1; o < 32; o <<= 1) {
        int t = __shfl_up_sync(0xffffffffu, s0, o);
        if (lane >= o) s0 += t;
    }
    int tot0 = __shfl_sync(0xffffffffu, s0, 31);
    int s1 = v1;
    #pragma unroll
    for (int o = 1; o < 32; o <<= 1) {
        int t = __shfl_up_sync(0xffffffffu, s1, o);
        if (lane >= o) s1 += t;
    }
    s1 += tot0;
    if (lane < NB)      g_bsum[lane]      = s0 - v0;   // exclusive
    if (lane + 32 < NB) g_bsum[lane + 32] = s1 - v1;
    if (lane == 0) g_off[0] = 0;
}

__global__ void k_scan3() {
    int tid = threadIdx.x;
    int i = blockIdx.x * SCAN_B + tid;
    if (i < N_NODES) g_off[i + 1] += g_bsum[blockIdx.x];
}

__global__ void k_fill(const int* __restrict__ src, const int* __restrict__ dst) {
    int e = blockIdx.x * blockDim.x + threadIdx.x;
    if (e < N_EDGES) {
        int d = dst[e];
        int s = src[e];
        int p = atomicAdd(&g_cnt[d], 1);
        int idx = g_off[d] + p;
        g_csr[idx] = make_int2(s, __float_as_int(g_dis[s]));
    }
}

// ---------------- TF32 tensor-core GEMM, cp.async 2-stage pipeline ----------------
// BM=128 BN=128 BK=16, 256 threads = 8 warps, warp tile 32x64 (2x8 m16n8k8 frags)
#define BM 128
#define BN 128
#define BK 16
#define ASTRIDE (BK + 4)    // 20 floats per A row -> conflict-free frag loads
#define BSTRIDE (BN + 8)    // 136 floats per B row -> conflict-free frag loads

__device__ __forceinline__ uint32_t f2tf32(float v) {
    uint32_t r;
    asm volatile("cvt.rna.tf32.f32 %0, %1;" : "=r"(r) : "f"(v));
    return r;
}

__device__ __forceinline__ void cp16(uint32_t saddr, const void* g, int sz) {
    asm volatile("cp.async.ca.shared.global [%0], [%1], 16, %2;" :: "r"(saddr), "l"(g), "r"(sz));
}
__device__ __forceinline__ void cp_commit() { asm volatile("cp.async.commit_group;"); }
__device__ __forceinline__ void cp_wait0()  { asm volatile("cp.async.wait_group 0;"); }

__global__ __launch_bounds__(256)
void k_gemm_tf32(const float* __restrict__ A,
                 const float* __restrict__ B0, const float* __restrict__ B1,
                 int ldb0, int ldb1, int splitB,
                 const float* __restrict__ bias0, const float* __restrict__ bias1,
                 float* __restrict__ out0, float* __restrict__ out1,
                 int M, int K, int N, int splitOut)
{
    __shared__ float As[2][BM][ASTRIDE];   // raw fp32, row-major [row][k]
    __shared__ float Bs[2][BK][BSTRIDE];   // raw fp32, [k][n]

    const int tid  = threadIdx.x;
    const int lane = tid & 31;
    const int wid  = tid >> 5;
    const int lrow = lane >> 2;   // 0..7
    const int lcol = lane & 3;    // 0..3

    const int row0 = blockIdx.y * BM;
    const int col0 = blockIdx.x * BN;

    const int wm0 = (wid & 3) * 32;
    const int wn0 = (wid >> 2) * 64;

    float acc[2][8][4];
    #pragma unroll
    for (int mi = 0; mi < 2; mi++)
        #pragma unroll
        for (int ni = 0; ni < 8; ni++)
            #pragma unroll
            for (int q = 0; q < 4; q++) acc[mi][ni][q] = 0.0f;

    // cp.async coordinates: 512 16B-chunks per tile each for A and B, 2 per thread
    // A chunk q: row=q>>2 (0..127), cseg=(q&3)*4
    // B chunk q: row=q>>5 (0..15),  nseg=(q&31)*4
    auto load_tile = [&](int s, int k0) {
        #pragma unroll
        for (int p = 0; p < 2; p++) {
            int q = tid + p * 256;
            int r = q >> 2;
            int c = (q & 3) * 4;
            int gr = row0 + r;
            int ok = (gr < M) ? 16 : 0;
            int grc = (gr < M) ? gr : (M - 1);
            uint32_t dstA = (uint32_t)__cvta_generic_to_shared(&As[s][r][c]);
            cp16(dstA, &A[(size_t)grc * K + k0 + c], ok);
        }
        #pragma unroll
        for (int p = 0; p < 2; p++) {
            int q = tid + p * 256;
            int r = q >> 5;
            int n = (q & 31) * 4;
            int cg = col0 + n;
            const float* gp = (cg < splitB)
                ? &B0[(size_t)(k0 + r) * ldb0 + cg]
                : &B1[(size_t)(k0 + r) * ldb1 + (cg - splitB)];
            uint32_t dstB = (uint32_t)__cvta_generic_to_shared(&Bs[s][r][n]);
            cp16(dstB, gp, 16);
        }
    };

    // prologue
    load_tile(0, 0);
    cp_commit();
    cp_wait0();
    __syncthreads();

    const int nIter = K / BK;
    int buf = 0;

    for (int it = 0; it < nIter; it++) {
        const bool has_next = (it + 1 < nIter);
        if (has_next) {
            load_tile(buf ^ 1, (it + 1) * BK);
            cp_commit();
        }

        // ---- compute from smem[buf], tf32 conversion on fragment path ----
        #pragma unroll
        for (int ks = 0; ks < BK; ks += 8) {
            uint32_t a[2][4];
            #pragma unroll
            for (int mi = 0; mi < 2; mi++) {
                int mr = wm0 + mi * 16 + lrow;
                a[mi][0] = f2tf32(As[buf][mr    ][ks + lcol    ]);
                a[mi][1] = f2tf32(As[buf][mr + 8][ks + lcol    ]);
                a[mi][2] = f2tf32(As[buf][mr    ][ks + 4 + lcol]);
                a[mi][3] = f2tf32(As[buf][mr + 8][ks + 4 + lcol]);
            }
            #pragma unroll
            for (int ni = 0; ni < 8; ni++) {
                int nc = wn0 + ni * 8 + lrow;
                uint32_t b0 = f2tf32(Bs[buf][ks + lcol    ][nc]);
                uint32_t b1 = f2tf32(Bs[buf][ks + 4 + lcol][nc]);
                #pragma unroll
                for (int mi = 0; mi < 2; mi++) {
                    asm volatile(
                        "mma.sync.aligned.m16n8k8.row.col.f32.tf32.tf32.f32 "
                        "{%0,%1,%2,%3}, {%4,%5,%6,%7}, {%8,%9}, {%0,%1,%2,%3};\n"
                        : "+f"(acc[mi][ni][0]), "+f"(acc[mi][ni][1]),
                          "+f"(acc[mi][ni][2]), "+f"(acc[mi][ni][3])
                        : "r"(a[mi][0]), "r"(a[mi][1]), "r"(a[mi][2]), "r"(a[mi][3]),
                          "r"(b0), "r"(b1));
                }
            }
        }

        if (has_next) cp_wait0();
        __syncthreads();
        buf ^= 1;
    }

    // ---- epilogue: bias + split store ----
    #pragma unroll
    for (int mi = 0; mi < 2; mi++) {
        #pragma unroll
        for (int half = 0; half < 2; half++) {
            int r = row0 + wm0 + mi * 16 + lrow + half * 8;
            if (r >= M) continue;
            #pragma unroll
            for (int ni = 0; ni < 8; ni++) {
                int c = col0 + wn0 + ni * 8 + lcol * 2;
                float v0 = acc[mi][ni][half * 2 + 0];
                float v1 = acc[mi][ni][half * 2 + 1];
                if (c < splitOut) {
                    if (bias0) { v0 += bias0[c]; v1 += bias0[c + 1]; }
                    *(float2*)&out0[(size_t)r * splitOut + c] = make_float2(v0, v1);
                } else {
                    int cc = c - splitOut;
                    if (bias1) { v0 += bias1[cc]; v1 += bias1[cc + 1]; }
                    *(float2*)&out1[(size_t)r * splitOut + cc] = make_float2(v0, v1);
                }
            }
        }
    }
}

// ---------------- CSR aggregation: out[n] = dis[n]*sum_e w_e*h[src_e] + selfn[n]*h[n] + b ----------------
__global__ void k_aggregate(const float* __restrict__ hin,
                            const float* __restrict__ bias,
                            float* __restrict__ hout,
                            int do_relu)
{
    int n = blockIdx.x;
    int t = threadIdx.x;            // 0..63, each owns 4 features
    int fo = t * 4;

    float4 acc = make_float4(0.f, 0.f, 0.f, 0.f);
    int beg = g_off[n], end = g_off[n + 1];

    int i = beg;
    for (; i + 4 <= end; i += 4) {
        int2 e0 = g_csr[i + 0];
        int2 e1 = g_csr[i + 1];
        int2 e2 = g_csr[i + 2];
        int2 e3 = g_csr[i + 3];
        float4 v0 = *(const float4*)&hin[(size_t)e0.x * HID_C + fo];
        float4 v1 = *(const float4*)&hin[(size_t)e1.x * HID_C + fo];
        float4 v2 = *(const float4*)&hin[(size_t)e2.x * HID_C + fo];
        float4 v3 = *(const float4*)&hin[(size_t)e3.x * HID_C + fo];
        float w0 = __int_as_float(e0.y);
        float w1 = __int_as_float(e1.y);
        float w2 = __int_as_float(e2.y);
        float w3 = __int_as_float(e3.y);
        acc.x = fmaf(w0, v0.x, acc.x); acc.y = fmaf(w0, v0.y, acc.y);
        acc.z = fmaf(w0, v0.z, acc.z); acc.w = fmaf(w0, v0.w, acc.w);
        acc.x = fmaf(w1, v1.x, acc.x); acc.y = fmaf(w1, v1.y, acc.y);
        acc.z = fmaf(w1, v1.z, acc.z); acc.w = fmaf(w1, v1.w, acc.w);
        acc.x = fmaf(w2, v2.x, acc.x); acc.y = fmaf(w2, v2.y, acc.y);
        acc.z = fmaf(w2, v2.z, acc.z); acc.w = fmaf(w2, v2.w, acc.w);
        acc.x = fmaf(w3, v3.x, acc.x); acc.y = fmaf(w3, v3.y, acc.y);
        acc.z = fmaf(w3, v3.z, acc.z); acc.w = fmaf(w3, v3.w, acc.w);
    }
    for (; i < end; i++) {
        int2 e = g_csr[i];
        float w = __int_as_float(e.y);
        float4 v = *(const float4*)&hin[(size_t)e.x * HID_C + fo];
        acc.x = fmaf(w, v.x, acc.x);
        acc.y = fmaf(w, v.y, acc.y);
        acc.z = fmaf(w, v.z, acc.z);
        acc.w = fmaf(w, v.w, acc.w);
    }

    float dn = g_dis[n];
    float sn = g_selfn[n];
    float4 hv = *(const float4*)&hin[(size_t)n * HID_C + fo];
    float4 r;
    float bx = bias ? bias[fo + 0] : 0.f;
    float by = bias ? bias[fo + 1] : 0.f;
    float bz = bias ? bias[fo + 2] : 0.f;
    float bw = bias ? bias[fo + 3] : 0.f;
    r.x = dn * acc.x + sn * hv.x + bx;
    r.y = dn * acc.y + sn * hv.y + by;
    r.z = dn * acc.z + sn * hv.z + bz;
    r.w = dn * acc.w + sn * hv.w + bw;
    if (do_relu) {
        r.x = fmaxf(r.x, 0.f);
        r.y = fmaxf(r.y, 0.f);
        r.z = fmaxf(r.z, 0.f);
        r.w = fmaxf(r.w, 0.f);
    }
    *(float4*)&hout[(size_t)n * HID_C + fo] = r;
}

// ---------------- launch ----------------
extern "C" void kernel_launch(void* const* d_in, const int* in_sizes, int n_in,
                              void* d_out, int out_size)
{
    const float* x    = (const float*)d_in[0];
    const int*   ei   = (const int*)  d_in[1];
    const float* w1   = (const float*)d_in[2];
    const float* b1   = (const float*)d_in[3];
    const float* w_mu = (const float*)d_in[4];
    const float* b_mu = (const float*)d_in[5];
    const float* w_ls = (const float*)d_in[6];
    const float* b_ls = (const float*)d_in[7];
    float* out = (float*)d_out;

    const int* src = ei;
    const int* dst = ei + N_EDGES;

    void *p_h1, *p_h, *p_g;
    cudaGetSymbolAddress(&p_h1, g_h1);
    cudaGetSymbolAddress(&p_h,  g_h);
    cudaGetSymbolAddress(&p_g,  g_g);
    float* h1 = (float*)p_h1;
    float* h  = (float*)p_h;
    float* g  = (float*)p_g;

    // fork: CSR build on side stream, overlapped with GEMM1 on main stream
    cudaEventRecord(g_aux.ev_fork, 0);
    cudaStreamWaitEvent(g_aux.s2, g_aux.ev_fork, 0);

    k_zero <<<(N_NODES + 255) / 256, 256, 0, g_aux.s2>>>();
    k_count<<<(N_EDGES + 255) / 256, 256, 0, g_aux.s2>>>(dst);
    k_scan1<<<NB, SCAN_B, 0, g_aux.s2>>>();
    k_scan2<<<1, 32, 0, g_aux.s2>>>();
    k_scan3<<<NB, SCAN_B, 0, g_aux.s2>>>();
    k_fill <<<(N_EDGES + 255) / 256, 256, 0, g_aux.s2>>>(src, dst);
    cudaEventRecord(g_aux.ev_join, g_aux.s2);

    // h1 = x @ w1 (main stream, overlaps CSR build)
    {
        dim3 grid(HID_C / BN, (N_NODES + BM - 1) / BM);
        k_gemm_tf32<<<grid, 256>>>(x, w1, w1, HID_C, HID_C, HID_C,
                                   nullptr, nullptr,
                                   h1, h1, N_NODES, IN_C, HID_C, HID_C);
    }

    // join before aggregation
    cudaStreamWaitEvent(0, g_aux.ev_join, 0);

    // h = relu(Â h1 + b1)
    k_aggregate<<<N_NODES, 64>>>(h1, b1, h, 1);

    // g = Â h
    k_aggregate<<<N_NODES, 64>>>(h, nullptr, g, 0);

    // [mu | logstd] = g @ [w_mu|w_ls] + [b_mu|b_ls] (direct two-pointer B, no concat)
    {
        dim3 grid((2 * OUT_C) / BN, (N_NODES + BM - 1) / BM);
        k_gemm_tf32<<<grid, 256>>>(g, w_mu, w_ls, OUT_C, OUT_C, OUT_C,
                                   b_mu, b_ls,
                                   out, out + (size_t)N_NODES * OUT_C,
                                   N_NODES, HID_C, 2 * OUT_C, OUT_C);
    }
}

// round 6
// speedup vs baseline: 2.4801x; 1.0708x over previous
#include <cuda_runtime.h>
#include <cuda_bf16.h>
#include <cstdint>
#include <cstddef>

#define N_NODES 50000
#define N_EDGES 500000
#define IN_C 512
#define HID_C 256
#define OUT_C 128

#define SCAN_B 1024
#define NB ((N_NODES + SCAN_B - 1) / SCAN_B)   // 49

// ---------------- scratch (device globals; no allocation) ----------------
__device__ int   g_degi[N_NODES];
__device__ int   g_cnt[N_NODES];
__device__ int   g_off[N_NODES + 1];
__device__ int   g_bsum[NB];
__device__ int2  g_csr[N_EDGES];              // (src, weight-as-bits)
__device__ float g_dis[N_NODES];
__device__ float g_selfn[N_NODES];
__device__ float g_h1[(size_t)N_NODES * HID_C];
__device__ float g_h [(size_t)N_NODES * HID_C];
__device__ float g_g [(size_t)N_NODES * HID_C];
__device__ float g_w1T [HID_C * IN_C];        // [n][k], tf32-rounded
__device__ float g_wcatT[(2 * OUT_C) * HID_C];// [n][k], tf32-rounded, [w_mu | w_ls]
__device__ float g_bcat[2 * OUT_C];

// ---------------- streams/events for capture fork-join (created pre-capture) ----------------
struct Aux {
    cudaStream_t s2;
    cudaEvent_t ev_fork, ev_join;
    Aux() {
        cudaStreamCreateWithFlags(&s2, cudaStreamNonBlocking);
        cudaEventCreateWithFlags(&ev_fork, cudaEventDisableTiming);
        cudaEventCreateWithFlags(&ev_join, cudaEventDisableTiming);
    }
};
static Aux g_aux;

__device__ __forceinline__ uint32_t f2tf32(float v) {
    uint32_t r;
    asm volatile("cvt.rna.tf32.f32 %0, %1;" : "=r"(r) : "f"(v));
    return r;
}
__device__ __forceinline__ float tf32r(float v) { return __uint_as_float(f2tf32(v)); }

// ---------------- CSR build ----------------
__global__ void k_zero() {
    int i = blockIdx.x * blockDim.x + threadIdx.x;
    if (i < N_NODES) { g_degi[i] = 0; g_cnt[i] = 0; }
}

__global__ void k_count(const int* __restrict__ dst) {
    int e = blockIdx.x * blockDim.x + threadIdx.x;
    if (e < N_EDGES) atomicAdd(&g_degi[dst[e]], 1);
}

__global__ void k_scan1() {
    __shared__ int sh[SCAN_B];
    int tid = threadIdx.x;
    int i = blockIdx.x * SCAN_B + tid;
    int v = (i < N_NODES) ? g_degi[i] : 0;
    if (i < N_NODES) {
        float degf = (float)v + 1.0f;
        g_dis[i]   = rsqrtf(degf);
        g_selfn[i] = 1.0f / degf;
    }
    sh[tid] = v;
    __syncthreads();
    for (int off = 1; off < SCAN_B; off <<= 1) {
        int t = (tid >= off) ? sh[tid - off] : 0;
        __syncthreads();
        sh[tid] += t;
        __syncthreads();
    }
    if (i < N_NODES) g_off[i + 1] = sh[tid];
    if (tid == SCAN_B - 1) g_bsum[blockIdx.x] = sh[tid];
}

__global__ void k_scan2() {
    int lane = threadIdx.x;
    int v0 = (lane < NB) ? g_bsum[lane] : 0;
    int v1 = (lane + 32 < NB) ? g_bsum[lane + 32] : 0;
    int s0 = v0;
    #pragma unroll
    for (int o = 1; o < 32; o <<= 1) {
        int t = __shfl_up_sync(0xffffffffu, s0, o);
        if (lane >= o) s0 += t;
    }
    int tot0 = __shfl_sync(0xffffffffu, s0, 31);
    int s1 = v1;
    #pragma unroll
    for (int o = 1; o < 32; o <<= 1) {
        int t = __shfl_up_sync(0xffffffffu, s1, o);
        if (lane >= o) s1 += t;
    }
    s1 += tot0;
    if (lane < NB)      g_bsum[lane]      = s0 - v0;
    if (lane + 32 < NB) g_bsum[lane + 32] = s1 - v1;
    if (lane == 0) g_off[0] = 0;
}

__global__ void k_scan3() {
    int tid = threadIdx.x;
    int i = blockIdx.x * SCAN_B + tid;
    if (i < N_NODES) g_off[i + 1] += g_bsum[blockIdx.x];
}

__global__ void k_fill(const int* __restrict__ src, const int* __restrict__ dst) {
    int e = blockIdx.x * blockDim.x + threadIdx.x;
    if (e < N_EDGES) {
        int d = dst[e];
        int s = src[e];
        int p = atomicAdd(&g_cnt[d], 1);
        int idx = g_off[d] + p;
        g_csr[idx] = make_int2(s, __float_as_int(g_dis[s]));
    }
}

// ---------------- weight transposes (n-major, tf32-rounded) ----------------
__global__ void k_w1T(const float* __restrict__ w1) {
    int i = blockIdx.x * blockDim.x + threadIdx.x;    // over HID_C*IN_C
    if (i < HID_C * IN_C) {
        int n = i / IN_C;
        int k = i % IN_C;
        g_w1T[i] = tf32r(w1[(size_t)k * HID_C + n]);
    }
}

__global__ void k_wcatT(const float* __restrict__ w_mu, const float* __restrict__ w_ls,
                        const float* __restrict__ b_mu, const float* __restrict__ b_ls) {
    int i = blockIdx.x * blockDim.x + threadIdx.x;    // over 256*256
    if (i < (2 * OUT_C) * HID_C) {
        int n = i / HID_C;
        int k = i % HID_C;
        float v = (n < OUT_C) ? w_mu[(size_t)k * OUT_C + n]
                              : w_ls[(size_t)k * OUT_C + (n - OUT_C)];
        g_wcatT[i] = tf32r(v);
    }
    if (i < 2 * OUT_C) {
        g_bcat[i] = (i < OUT_C) ? b_mu[i] : b_ls[i - OUT_C];
    }
}

// ---------------- TF32 tensor-core GEMM: ldmatrix + cp.async ----------------
// BM=128 BN=128 BK=16, 256 threads = 8 warps, warp tile 32x64 (2x8 m16n8k8)
// A in smem [m][k] stride 20; B in smem [n][k] stride 20 (from pre-transposed BT).
#define BM 128
#define BN 128
#define BK 16
#define SSTRIDE 20

__device__ __forceinline__ void cp16(uint32_t saddr, const void* g, int sz) {
    asm volatile("cp.async.ca.shared.global [%0], [%1], 16, %2;" :: "r"(saddr), "l"(g), "r"(sz));
}
__device__ __forceinline__ void cp_commit() { asm volatile("cp.async.commit_group;"); }
__device__ __forceinline__ void cp_wait0()  { asm volatile("cp.async.wait_group 0;"); }

__device__ __forceinline__ void ldsm4(uint32_t& r0, uint32_t& r1, uint32_t& r2, uint32_t& r3,
                                      uint32_t addr) {
    asm volatile("ldmatrix.sync.aligned.m8n8.x4.shared.b16 {%0,%1,%2,%3}, [%4];"
                 : "=r"(r0), "=r"(r1), "=r"(r2), "=r"(r3) : "r"(addr));
}

template<bool CVTA>
__global__ __launch_bounds__(256, 2)
void k_gemm_tf32(const float* __restrict__ A, const float* __restrict__ BT,
                 const float* __restrict__ bias,
                 float* __restrict__ out0, float* __restrict__ out1,
                 int M, int K, int splitOut)
{
    __shared__ float As[2][BM][SSTRIDE];   // [m][k]
    __shared__ float Bs[2][BN][SSTRIDE];   // [n][k]

    const int tid  = threadIdx.x;
    const int lane = tid & 31;
    const int wid  = tid >> 5;

    const int row0 = blockIdx.y * BM;
    const int col0 = blockIdx.x * BN;

    const int wm0 = (wid & 3) * 32;
    const int wn0 = (wid >> 2) * 64;

    // ldmatrix lane-address decomposition
    const int lr  = lane & 7;
    const int sel = lane >> 3;                 // 0..3
    const int a_ro = ((sel & 1) << 3) + lr;    // +8 rows for a1/a3
    const int a_co = (sel >> 1) << 2;          // +4 k for a2/a3
    const int b_ro = ((sel >> 1) << 3) + lr;   // +8 n for second ni
    const int b_co = (sel & 1) << 2;           // +4 k for b1

    float acc[2][8][4];
    #pragma unroll
    for (int mi = 0; mi < 2; mi++)
        #pragma unroll
        for (int ni = 0; ni < 8; ni++)
            #pragma unroll
            for (int q = 0; q < 4; q++) acc[mi][ni][q] = 0.0f;

    // cp.async: 512 16B chunks per tile each for A and B, 2 per thread each
    auto load_tile = [&](int s, int k0) {
        #pragma unroll
        for (int p = 0; p < 2; p++) {
            int q = tid + p * 256;
            int r = q >> 2;
            int c = (q & 3) * 4;
            int gr = row0 + r;
            int ok = (gr < M) ? 16 : 0;
            int grc = (gr < M) ? gr : (M - 1);
            uint32_t dstA = (uint32_t)__cvta_generic_to_shared(&As[s][r][c]);
            cp16(dstA, &A[(size_t)grc * K + k0 + c], ok);
        }
        #pragma unroll
        for (int p = 0; p < 2; p++) {
            int q = tid + p * 256;
            int r = q >> 2;
            int c = (q & 3) * 4;
            uint32_t dstB = (uint32_t)__cvta_generic_to_shared(&Bs[s][r][c]);
            cp16(dstB, &BT[(size_t)(col0 + r) * K + k0 + c], 16);
        }
    };

    load_tile(0, 0);
    cp_commit();
    cp_wait0();
    __syncthreads();

    const int nIter = K / BK;
    int buf = 0;

    for (int it = 0; it < nIter; it++) {
        const bool has_next = (it + 1 < nIter);
        if (has_next) {
            load_tile(buf ^ 1, (it + 1) * BK);
            cp_commit();
        }

        #pragma unroll
        for (int ks = 0; ks < BK; ks += 8) {
            uint32_t a[2][4];
            #pragma unroll
            for (int mi = 0; mi < 2; mi++) {
                uint32_t addr = (uint32_t)__cvta_generic_to_shared(
                    &As[buf][wm0 + mi * 16 + a_ro][ks + a_co]);
                ldsm4(a[mi][0], a[mi][1], a[mi][2], a[mi][3], addr);
                if (CVTA) {
                    a[mi][0] = f2tf32(__uint_as_float(a[mi][0]));
                    a[mi][1] = f2tf32(__uint_as_float(a[mi][1]));
                    a[mi][2] = f2tf32(__uint_as_float(a[mi][2]));
                    a[mi][3] = f2tf32(__uint_as_float(a[mi][3]));
                }
            }
            #pragma unroll
            for (int np = 0; np < 4; np++) {
                uint32_t bb[4];
                uint32_t addr = (uint32_t)__cvta_generic_to_shared(
                    &Bs[buf][wn0 + np * 16 + b_ro][ks + b_co]);
                ldsm4(bb[0], bb[1], bb[2], bb[3], addr);
                #pragma unroll
                for (int par = 0; par < 2; par++) {
                    int ni = np * 2 + par;
                    uint32_t b0 = bb[par * 2 + 0];
                    uint32_t b1 = bb[par * 2 + 1];
                    #pragma unroll
                    for (int mi = 0; mi < 2; mi++) {
                        asm volatile(
                            "mma.sync.aligned.m16n8k8.row.col.f32.tf32.tf32.f32 "
                            "{%0,%1,%2,%3}, {%4,%5,%6,%7}, {%8,%9}, {%0,%1,%2,%3};\n"
                            : "+f"(acc[mi][ni][0]), "+f"(acc[mi][ni][1]),
                              "+f"(acc[mi][ni][2]), "+f"(acc[mi][ni][3])
                            : "r"(a[mi][0]), "r"(a[mi][1]), "r"(a[mi][2]), "r"(a[mi][3]),
                              "r"(b0), "r"(b1));
                    }
                }
            }
        }

        if (has_next) cp_wait0();
        __syncthreads();
        buf ^= 1;
    }

    // ---- epilogue: bias + split store ----
    const int lrow = lane >> 2;
    const int lcol = lane & 3;
    #pragma unroll
    for (int mi = 0; mi < 2; mi++) {
        #pragma unroll
        for (int half = 0; half < 2; half++) {
            int r = row0 + wm0 + mi * 16 + lrow + half * 8;
            if (r >= M) continue;
            #pragma unroll
            for (int ni = 0; ni < 8; ni++) {
                int c = col0 + wn0 + ni * 8 + lcol * 2;
                float v0 = acc[mi][ni][half * 2 + 0];
                float v1 = acc[mi][ni][half * 2 + 1];
                if (bias) { v0 += bias[c]; v1 += bias[c + 1]; }
                if (c < splitOut) {
                    *(float2*)&out0[(size_t)r * splitOut + c] = make_float2(v0, v1);
                } else {
                    *(float2*)&out1[(size_t)r * splitOut + (c - splitOut)] = make_float2(v0, v1);
                }
            }
        }
    }
}

// ---------------- CSR aggregation ----------------
__global__ void k_aggregate(const float* __restrict__ hin,
                            const float* __restrict__ bias,
                            float* __restrict__ hout,
                            int do_relu, int cvt_out)
{
    int n = blockIdx.x;
    int t = threadIdx.x;            // 0..63, each owns 4 features
    int fo = t * 4;

    float4 acc = make_float4(0.f, 0.f, 0.f, 0.f);
    int beg = g_off[n], end = g_off[n + 1];

    int i = beg;
    for (; i + 4 <= end; i += 4) {
        int2 e0 = g_csr[i + 0];
        int2 e1 = g_csr[i + 1];
        int2 e2 = g_csr[i + 2];
        int2 e3 = g_csr[i + 3];
        float4 v0 = *(const float4*)&hin[(size_t)e0.x * HID_C + fo];
        float4 v1 = *(const float4*)&hin[(size_t)e1.x * HID_C + fo];
        float4 v2 = *(const float4*)&hin[(size_t)e2.x * HID_C + fo];
        float4 v3 = *(const float4*)&hin[(size_t)e3.x * HID_C + fo];
        float w0 = __int_as_float(e0.y);
        float w1 = __int_as_float(e1.y);
        float w2 = __int_as_float(e2.y);
        float w3 = __int_as_float(e3.y);
        acc.x = fmaf(w0, v0.x, acc.x); acc.y = fmaf(w0, v0.y, acc.y);
        acc.z = fmaf(w0, v0.z, acc.z); acc.w = fmaf(w0, v0.w, acc.w);
        acc.x = fmaf(w1, v1.x, acc.x); acc.y = fmaf(w1, v1.y, acc.y);
        acc.z = fmaf(w1, v1.z, acc.z); acc.w = fmaf(w1, v1.w, acc.w);
        acc.x = fmaf(w2, v2.x, acc.x); acc.y = fmaf(w2, v2.y, acc.y);
        acc.z = fmaf(w2, v2.z, acc.z); acc.w = fmaf(w2, v2.w, acc.w);
        acc.x = fmaf(w3, v3.x, acc.x); acc.y = fmaf(w3, v3.y, acc.y);
        acc.z = fmaf(w3, v3.z, acc.z); acc.w = fmaf(w3, v3.w, acc.w);
    }
    for (; i < end; i++) {
        int2 e = g_csr[i];
        float w = __int_as_float(e.y);
        float4 v = *(const float4*)&hin[(size_t)e.x * HID_C + fo];
        acc.x = fmaf(w, v.x, acc.x);
        acc.y = fmaf(w, v.y, acc.y);
        acc.z = fmaf(w, v.z, acc.z);
        acc.w = fmaf(w, v.w, acc.w);
    }

    float dn = g_dis[n];
    float sn = g_selfn[n];
    float4 hv = *(const float4*)&hin[(size_t)n * HID_C + fo];
    float4 r;
    float bx = bias ? bias[fo + 0] : 0.f;
    float by = bias ? bias[fo + 1] : 0.f;
    float bz = bias ? bias[fo + 2] : 0.f;
    float bw = bias ? bias[fo + 3] : 0.f;
    r.x = dn * acc.x + sn * hv.x + bx;
    r.y = dn * acc.y + sn * hv.y + by;
    r.z = dn * acc.z + sn * hv.z + bz;
    r.w = dn * acc.w + sn * hv.w + bw;
    if (do_relu) {
        r.x = fmaxf(r.x, 0.f);
        r.y = fmaxf(r.y, 0.f);
        r.z = fmaxf(r.z, 0.f);
        r.w = fmaxf(r.w, 0.f);
    }
    if (cvt_out) {
        r.x = tf32r(r.x); r.y = tf32r(r.y); r.z = tf32r(r.z); r.w = tf32r(r.w);
    }
    *(float4*)&hout[(size_t)n * HID_C + fo] = r;
}

// ---------------- launch ----------------
extern "C" void kernel_launch(void* const* d_in, const int* in_sizes, int n_in,
                              void* d_out, int out_size)
{
    const float* x    = (const float*)d_in[0];
    const int*   ei   = (const int*)  d_in[1];
    const float* w1   = (const float*)d_in[2];
    const float* b1   = (const float*)d_in[3];
    const float* w_mu = (const float*)d_in[4];
    const float* b_mu = (const float*)d_in[5];
    const float* w_ls = (const float*)d_in[6];
    const float* b_ls = (const float*)d_in[7];
    float* out = (float*)d_out;

    const int* src = ei;
    const int* dst = ei + N_EDGES;

    void *p_h1, *p_h, *p_g, *p_w1T, *p_wcatT, *p_bcat;
    cudaGetSymbolAddress(&p_h1,    g_h1);
    cudaGetSymbolAddress(&p_h,     g_h);
    cudaGetSymbolAddress(&p_g,     g_g);
    cudaGetSymbolAddress(&p_w1T,   g_w1T);
    cudaGetSymbolAddress(&p_wcatT, g_wcatT);
    cudaGetSymbolAddress(&p_bcat,  g_bcat);
    float* h1    = (float*)p_h1;
    float* h     = (float*)p_h;
    float* g     = (float*)p_g;
    float* w1T   = (float*)p_w1T;
    float* wcatT = (float*)p_wcatT;
    float* bcat  = (float*)p_bcat;

    // fork: CSR build + wcatT on side stream, overlapped with w1T + GEMM1
    cudaEventRecord(g_aux.ev_fork, 0);
    cudaStreamWaitEvent(g_aux.s2, g_aux.ev_fork, 0);

    k_zero <<<(N_NODES + 255) / 256, 256, 0, g_aux.s2>>>();
    k_count<<<(N_EDGES + 255) / 256, 256, 0, g_aux.s2>>>(dst);
    k_scan1<<<NB, SCAN_B, 0, g_aux.s2>>>();
    k_scan2<<<1, 32, 0, g_aux.s2>>>();
    k_scan3<<<NB, SCAN_B, 0, g_aux.s2>>>();
    k_fill <<<(N_EDGES + 255) / 256, 256, 0, g_aux.s2>>>(src, dst);
    k_wcatT<<<((2 * OUT_C) * HID_C + 255) / 256, 256, 0, g_aux.s2>>>(w_mu, w_ls, b_mu, b_ls);
    cudaEventRecord(g_aux.ev_join, g_aux.s2);

    // main stream: transpose w1, then GEMM1 (overlaps CSR build)
    k_w1T<<<(HID_C * IN_C + 255) / 256, 256>>>(w1);
    {
        dim3 grid(HID_C / BN, (N_NODES + BM - 1) / BM);
        k_gemm_tf32<true><<<grid, 256>>>(x, w1T, nullptr,
                                         h1, h1, N_NODES, IN_C, HID_C);
    }

    // join before aggregation
    cudaStreamWaitEvent(0, g_aux.ev_join, 0);

    // h = relu(Â h1 + b1)
    k_aggregate<<<N_NODES, 64>>>(h1, b1, h, 1, 0);

    // g = Â h (tf32-rounded: feeds only GEMM2's A operand)
    k_aggregate<<<N_NODES, 64>>>(h, nullptr, g, 0, 1);

    // [mu | logstd] = g @ wcat + bcat (A pre-rounded -> no cvt in kernel)
    {
        dim3 grid((2 * OUT_C) / BN, (N_NODES + BM - 1) / BM);
        k_gemm_tf32<false><<<grid, 256>>>(g, wcatT, bcat,
                                          out, out + (size_t)N_NODES * OUT_C,
                                          N_NODES, HID_C, OUT_C);
    }
}

// round 9
// speedup vs baseline: 2.9338x; 1.1830x over previous
#include <cuda_runtime.h>
#include <cuda_fp16.h>
#include <cstdint>
#include <cstddef>
#include <cstring>

#define N_NODES 50000
#define N_EDGES 500000
#define IN_C 512
#define HID_C 256
#define OUT_C 128

#define SCAN_B 1024
#define NB ((N_NODES + SCAN_B - 1) / SCAN_B)   // 49

// ---------------- scratch (device globals; no allocation) ----------------
__device__ int    g_degi[N_NODES];
__device__ int    g_cnt[N_NODES];
__device__ int    g_off[N_NODES + 1];
__device__ int    g_bsum[NB];
__device__ int2   g_csr[N_EDGES];             // (src, weight-as-bits fp32)
__device__ float  g_dis[N_NODES];
__device__ float  g_selfn[N_NODES];
__device__ __half g_xh  [(size_t)N_NODES * IN_C];   // x in fp16
__device__ __half g_h1h [(size_t)N_NODES * HID_C];  // GEMM1 out (fp16)
__device__ __half g_hh  [(size_t)N_NODES * HID_C];  // relu-agg out (fp16)
__device__ __half g_gh  [(size_t)N_NODES * HID_C];  // second agg out (fp16)
__device__ __half g_w1Th [HID_C * IN_C];            // [n][k] fp16
__device__ __half g_wcatTh[(2 * OUT_C) * HID_C];    // [n][k] fp16, [w_mu | w_ls]

// ---------------- bit-cast helpers (missing intrinsics in this toolkit) ----------------
__device__ __forceinline__ uint32_t h2_as_u32(__half2 h) {
    uint32_t u; memcpy(&u, &h, 4); return u;
}
__device__ __forceinline__ __half2 u32_as_h2(uint32_t u) {
    __half2 h; memcpy(&h, &u, 4); return h;
}

// ---------------- streams/events for capture fork-join (created pre-capture) ----------------
struct Aux {
    cudaStream_t s2;
    cudaEvent_t ev_fork, ev_join;
    Aux() {
        cudaStreamCreateWithFlags(&s2, cudaStreamNonBlocking);
        cudaEventCreateWithFlags(&ev_fork, cudaEventDisableTiming);
        cudaEventCreateWithFlags(&ev_join, cudaEventDisableTiming);
    }
};
static Aux g_aux;

// ---------------- CSR build ----------------
__global__ void k_zero() {
    int i = blockIdx.x * blockDim.x + threadIdx.x;
    if (i < N_NODES) { g_degi[i] = 0; g_cnt[i] = 0; }
}

__global__ void k_count(const int* __restrict__ dst) {
    int e = blockIdx.x * blockDim.x + threadIdx.x;
    if (e < N_EDGES) atomicAdd(&g_degi[dst[e]], 1);
}

__global__ void k_scan1() {
    __shared__ int sh[SCAN_B];
    int tid = threadIdx.x;
    int i = blockIdx.x * SCAN_B + tid;
    int v = (i < N_NODES) ? g_degi[i] : 0;
    if (i < N_NODES) {
        float degf = (float)v + 1.0f;
        g_dis[i]   = rsqrtf(degf);
        g_selfn[i] = 1.0f / degf;
    }
    sh[tid] = v;
    __syncthreads();
    for (int off = 1; off < SCAN_B; off <<= 1) {
        int t = (tid >= off) ? sh[tid - off] : 0;
        __syncthreads();
        sh[tid] += t;
        __syncthreads();
    }
    if (i < N_NODES) g_off[i + 1] = sh[tid];
    if (tid == SCAN_B - 1) g_bsum[blockIdx.x] = sh[tid];
}

__global__ void k_scan2() {
    int lane = threadIdx.x;
    int v0 = (lane < NB) ? g_bsum[lane] : 0;
    int v1 = (lane + 32 < NB) ? g_bsum[lane + 32] : 0;
    int s0 = v0;
    #pragma unroll
    for (int o = 1; o < 32; o <<= 1) {
        int t = __shfl_up_sync(0xffffffffu, s0, o);
        if (lane >= o) s0 += t;
    }
    int tot0 = __shfl_sync(0xffffffffu, s0, 31);
    int s1 = v1;
    #pragma unroll
    for (int o = 1; o < 32; o <<= 1) {
        int t = __shfl_up_sync(0xffffffffu, s1, o);
        if (lane >= o) s1 += t;
    }
    s1 += tot0;
    if (lane < NB)      g_bsum[lane]      = s0 - v0;
    if (lane + 32 < NB) g_bsum[lane + 32] = s1 - v1;
    if (lane == 0) g_off[0] = 0;
}

__global__ void k_scan3() {
    int tid = threadIdx.x;
    int i = blockIdx.x * SCAN_B + tid;
    if (i < N_NODES) g_off[i + 1] += g_bsum[blockIdx.x];
}

__global__ void k_fill(const int* __restrict__ src, const int* __restrict__ dst) {
    int e = blockIdx.x * blockDim.x + threadIdx.x;
    if (e < N_EDGES) {
        int d = dst[e];
        int s = src[e];
        int p = atomicAdd(&g_cnt[d], 1);
        int idx = g_off[d] + p;
        g_csr[idx] = make_int2(s, __float_as_int(g_dis[s]));
    }
}

// ---------------- conversions: x -> fp16, weight transposes [n][k] fp16 ----------------
__global__ void k_xh(const float* __restrict__ x) {
    size_t i = (size_t)blockIdx.x * blockDim.x + threadIdx.x;  // over N*IN_C/8
    if (i < (size_t)N_NODES * IN_C / 8) {
        float4 a = ((const float4*)x)[i * 2 + 0];
        float4 b = ((const float4*)x)[i * 2 + 1];
        uint4 o;
        o.x = h2_as_u32(__floats2half2_rn(a.x, a.y));
        o.y = h2_as_u32(__floats2half2_rn(a.z, a.w));
        o.z = h2_as_u32(__floats2half2_rn(b.x, b.y));
        o.w = h2_as_u32(__floats2half2_rn(b.z, b.w));
        ((uint4*)g_xh)[i] = o;
    }
}

__global__ void k_w1T(const float* __restrict__ w1) {
    int i = blockIdx.x * blockDim.x + threadIdx.x;    // over HID_C*IN_C
    if (i < HID_C * IN_C) {
        int n = i / IN_C;
        int k = i % IN_C;
        g_w1Th[i] = __float2half_rn(w1[(size_t)k * HID_C + n]);
    }
}

__global__ void k_wcatT(const float* __restrict__ w_mu, const float* __restrict__ w_ls) {
    int i = blockIdx.x * blockDim.x + threadIdx.x;    // over 256*256
    if (i < (2 * OUT_C) * HID_C) {
        int n = i / HID_C;
        int k = i % HID_C;
        float v = (n < OUT_C) ? w_mu[(size_t)k * OUT_C + n]
                              : w_ls[(size_t)k * OUT_C + (n - OUT_C)];
        g_wcatTh[i] = __float2half_rn(v);
    }
}

// ---------------- fp16 tensor-core GEMM: ldmatrix + cp.async ----------------
// BM=128 BN=128 BK=16(halves), 256 threads = 8 warps, warp tile 32x64 (2x8 m16n8k16)
// A smem [m][k] stride 24 halves; B smem [n][k] stride 24 (pre-transposed BT).
#define BM 128
#define BN 128
#define BKH 16
#define SSH 24     // 48B row stride: 8-row ldmatrix addrs distinct mod 128B

__device__ __forceinline__ void cp16(uint32_t saddr, const void* g, int sz) {
    asm volatile("cp.async.ca.shared.global [%0], [%1], 16, %2;" :: "r"(saddr), "l"(g), "r"(sz));
}
__device__ __forceinline__ void cp_commit() { asm volatile("cp.async.commit_group;"); }
__device__ __forceinline__ void cp_wait0()  { asm volatile("cp.async.wait_group 0;"); }

__device__ __forceinline__ void ldsm4(uint32_t& r0, uint32_t& r1, uint32_t& r2, uint32_t& r3,
                                      uint32_t addr) {
    asm volatile("ldmatrix.sync.aligned.m8n8.x4.shared.b16 {%0,%1,%2,%3}, [%4];"
                 : "=r"(r0), "=r"(r1), "=r"(r2), "=r"(r3) : "r"(addr));
}

template<bool HALF_OUT>
__global__ __launch_bounds__(256)
void k_gemm_f16(const __half* __restrict__ A, const __half* __restrict__ BT,
                const float* __restrict__ bias0, const float* __restrict__ bias1,
                void* __restrict__ out0v, void* __restrict__ out1v,
                int M, int K, int splitOut)
{
    __shared__ __half As[2][BM][SSH];
    __shared__ __half Bs[2][BN][SSH];

    const int tid  = threadIdx.x;
    const int lane = tid & 31;
    const int wid  = tid >> 5;

    const int row0 = blockIdx.y * BM;
    const int col0 = blockIdx.x * BN;

    const int wm0 = (wid & 3) * 32;
    const int wn0 = (wid >> 2) * 64;

    // ldmatrix lane-address decomposition (halves)
    const int lr  = lane & 7;
    const int sel = lane >> 3;                 // 0..3
    const int a_ro = ((sel & 1) << 3) + lr;    // +8 rows for groups 1,3
    const int a_co = (sel >> 1) << 3;          // +8 halves (k) for groups 2,3
    const int b_ro = ((sel >> 1) << 3) + lr;   // +8 n-rows for groups 2,3
    const int b_co = (sel & 1) << 3;           // +8 halves (k) for groups 1,3

    float acc[2][8][4];
    #pragma unroll
    for (int mi = 0; mi < 2; mi++)
        #pragma unroll
        for (int ni = 0; ni < 8; ni++)
            #pragma unroll
            for (int q = 0; q < 4; q++) acc[mi][ni][q] = 0.0f;

    // cp.async: 256 16B chunks per tile each for A and B, 1 per thread each
    const int t_r = tid >> 1;              // 0..127
    const int t_c = (tid & 1) * 8;         // 0 or 8 halves
    auto load_tile = [&](int s, int k0) {
        int gr = row0 + t_r;
        int ok = (gr < M) ? 16 : 0;
        int grc = (gr < M) ? gr : (M - 1);
        cp16((uint32_t)__cvta_generic_to_shared(&As[s][t_r][t_c]),
             &A[(size_t)grc * K + k0 + t_c], ok);
        cp16((uint32_t)__cvta_generic_to_shared(&Bs[s][t_r][t_c]),
             &BT[(size_t)(col0 + t_r) * K + k0 + t_c], 16);
    };

    load_tile(0, 0);
    cp_commit();
    cp_wait0();
    __syncthreads();

    const int nIter = K / BKH;
    int buf = 0;

    for (int it = 0; it < nIter; it++) {
        const bool has_next = (it + 1 < nIter);
        if (has_next) {
            load_tile(buf ^ 1, (it + 1) * BKH);
            cp_commit();
        }

        uint32_t a[2][4];
        #pragma unroll
        for (int mi = 0; mi < 2; mi++) {
            uint32_t addr = (uint32_t)__cvta_generic_to_shared(
                &As[buf][wm0 + mi * 16 + a_ro][a_co]);
            ldsm4(a[mi][0], a[mi][1], a[mi][2], a[mi][3], addr);
        }
        #pragma unroll
        for (int np = 0; np < 4; np++) {
            uint32_t bb[4];
            uint32_t addr = (uint32_t)__cvta_generic_to_shared(
                &Bs[buf][wn0 + np * 16 + b_ro][b_co]);
            ldsm4(bb[0], bb[1], bb[2], bb[3], addr);
            #pragma unroll
            for (int par = 0; par < 2; par++) {
                int ni = np * 2 + par;
                uint32_t b0 = bb[par * 2 + 0];
                uint32_t b1 = bb[par * 2 + 1];
                #pragma unroll
                for (int mi = 0; mi < 2; mi++) {
                    asm volatile(
                        "mma.sync.aligned.m16n8k16.row.col.f32.f16.f16.f32 "
                        "{%0,%1,%2,%3}, {%4,%5,%6,%7}, {%8,%9}, {%0,%1,%2,%3};\n"
                        : "+f"(acc[mi][ni][0]), "+f"(acc[mi][ni][1]),
                          "+f"(acc[mi][ni][2]), "+f"(acc[mi][ni][3])
                        : "r"(a[mi][0]), "r"(a[mi][1]), "r"(a[mi][2]), "r"(a[mi][3]),
                          "r"(b0), "r"(b1));
                }
            }
        }

        if (has_next) cp_wait0();
        __syncthreads();
        buf ^= 1;
    }

    // ---- epilogue: bias + split store ----
    const int lrow = lane >> 2;
    const int lcol = lane & 3;
    #pragma unroll
    for (int mi = 0; mi < 2; mi++) {
        #pragma unroll
        for (int half = 0; half < 2; half++) {
            int r = row0 + wm0 + mi * 16 + lrow + half * 8;
            if (r >= M) continue;
            #pragma unroll
            for (int ni = 0; ni < 8; ni++) {
                int c = col0 + wn0 + ni * 8 + lcol * 2;
                float v0 = acc[mi][ni][half * 2 + 0];
                float v1 = acc[mi][ni][half * 2 + 1];
                if (c < splitOut) {
                    if (bias0) { v0 += bias0[c]; v1 += bias0[c + 1]; }
                    if (HALF_OUT) {
                        __half2* p = (__half2*)((__half*)out0v + (size_t)r * splitOut + c);
                        *p = __floats2half2_rn(v0, v1);
                    } else {
                        *(float2*)((float*)out0v + (size_t)r * splitOut + c) = make_float2(v0, v1);
                    }
                } else {
                    int cc = c - splitOut;
                    if (bias1) { v0 += bias1[cc]; v1 += bias1[cc + 1]; }
                    if (HALF_OUT) {
                        __half2* p = (__half2*)((__half*)out1v + (size_t)r * splitOut + cc);
                        *p = __floats2half2_rn(v0, v1);
                    } else {
                        *(float2*)((float*)out1v + (size_t)r * splitOut + cc) = make_float2(v0, v1);
                    }
                }
            }
        }
    }
}

// ---------------- CSR aggregation (fp16 in/out, fp32 accumulate) ----------------
// out[n] = dis[n]*sum_e w_e*h[src_e] + selfn[n]*h[n] + b   (+relu)
__global__ void k_aggregate(const __half* __restrict__ hin,
                            const float* __restrict__ bias,
                            __half* __restrict__ hout,
                            int do_relu)
{
    int n = blockIdx.x;
    int t = threadIdx.x;            // 0..31, each owns 8 features
    int fo = t * 8;

    float acc[8];
    #pragma unroll
    for (int j = 0; j < 8; j++) acc[j] = 0.0f;

    int beg = g_off[n], end = g_off[n + 1];

    auto accum = [&](int2 e) {
        float w = __int_as_float(e.y);
        uint4 v = *(const uint4*)&hin[(size_t)e.x * HID_C + fo];
        float2 f0 = __half22float2(u32_as_h2(v.x));
        float2 f1 = __half22float2(u32_as_h2(v.y));
        float2 f2 = __half22float2(u32_as_h2(v.z));
        float2 f3 = __half22float2(u32_as_h2(v.w));
        acc[0] = fmaf(w, f0.x, acc[0]); acc[1] = fmaf(w, f0.y, acc[1]);
        acc[2] = fmaf(w, f1.x, acc[2]); acc[3] = fmaf(w, f1.y, acc[3]);
        acc[4] = fmaf(w, f2.x, acc[4]); acc[5] = fmaf(w, f2.y, acc[5]);
        acc[6] = fmaf(w, f3.x, acc[6]); acc[7] = fmaf(w, f3.y, acc[7]);
    };

    int i = beg;
    for (; i + 4 <= end; i += 4) {
        int2 e0 = g_csr[i + 0];
        int2 e1 = g_csr[i + 1];
        int2 e2 = g_csr[i + 2];
        int2 e3 = g_csr[i + 3];
        accum(e0); accum(e1); accum(e2); accum(e3);
    }
    for (; i < end; i++) accum(g_csr[i]);

    float dn = g_dis[n];
    float sn = g_selfn[n];
    uint4 hv = *(const uint4*)&hin[(size_t)n * HID_C + fo];
    float2 s0 = __half22float2(u32_as_h2(hv.x));
    float2 s1 = __half22float2(u32_as_h2(hv.y));
    float2 s2 = __half22float2(u32_as_h2(hv.z));
    float2 s3 = __half22float2(u32_as_h2(hv.w));
    float sv[8] = {s0.x, s0.y, s1.x, s1.y, s2.x, s2.y, s3.x, s3.y};

    float r[8];
    #pragma unroll
    for (int j = 0; j < 8; j++) {
        float b = bias ? bias[fo + j] : 0.0f;
        r[j] = dn * acc[j] + sn * sv[j] + b;
        if (do_relu) r[j] = fmaxf(r[j], 0.0f);
    }
    uint4 o;
    o.x = h2_as_u32(__floats2half2_rn(r[0], r[1]));
    o.y = h2_as_u32(__floats2half2_rn(r[2], r[3]));
    o.z = h2_as_u32(__floats2half2_rn(r[4], r[5]));
    o.w = h2_as_u32(__floats2half2_rn(r[6], r[7]));
    *(uint4*)&hout[(size_t)n * HID_C + fo] = o;
}

// ---------------- launch ----------------
extern "C" void kernel_launch(void* const* d_in, const int* in_sizes, int n_in,
                              void* d_out, int out_size)
{
    const float* x    = (const float*)d_in[0];
    const int*   ei   = (const int*)  d_in[1];
    const float* w1   = (const float*)d_in[2];
    const float* b1   = (const float*)d_in[3];
    const float* w_mu = (const float*)d_in[4];
    const float* b_mu = (const float*)d_in[5];
    const float* w_ls = (const float*)d_in[6];
    const float* b_ls = (const float*)d_in[7];
    float* out = (float*)d_out;

    const int* src = ei;
    const int* dst = ei + N_EDGES;

    void *p_xh, *p_h1h, *p_hh, *p_gh, *p_w1Th, *p_wcatTh;
    cudaGetSymbolAddress(&p_xh,     g_xh);
    cudaGetSymbolAddress(&p_h1h,    g_h1h);
    cudaGetSymbolAddress(&p_hh,     g_hh);
    cudaGetSymbolAddress(&p_gh,     g_gh);
    cudaGetSymbolAddress(&p_w1Th,   g_w1Th);
    cudaGetSymbolAddress(&p_wcatTh, g_wcatTh);
    __half* xh     = (__half*)p_xh;
    __half* h1h    = (__half*)p_h1h;
    __half* hh     = (__half*)p_hh;
    __half* gh     = (__half*)p_gh;
    __half* w1Th   = (__half*)p_w1Th;
    __half* wcatTh = (__half*)p_wcatTh;

    // fork: CSR build + wcatT on side stream
    cudaEventRecord(g_aux.ev_fork, 0);
    cudaStreamWaitEvent(g_aux.s2, g_aux.ev_fork, 0);

    k_zero <<<(N_NODES + 255) / 256, 256, 0, g_aux.s2>>>();
    k_count<<<(N_EDGES + 255) / 256, 256, 0, g_aux.s2>>>(dst);
    k_scan1<<<NB, SCAN_B, 0, g_aux.s2>>>();
    k_scan2<<<1, 32, 0, g_aux.s2>>>();
    k_scan3<<<NB, SCAN_B, 0, g_aux.s2>>>();
    k_fill <<<(N_EDGES + 255) / 256, 256, 0, g_aux.s2>>>(src, dst);
    k_wcatT<<<((2 * OUT_C) * HID_C + 255) / 256, 256, 0, g_aux.s2>>>(w_mu, w_ls);
    cudaEventRecord(g_aux.ev_join, g_aux.s2);

    // main stream: x->fp16, transpose w1, GEMM1 (overlaps CSR build)
    k_xh <<<((int)((size_t)N_NODES * IN_C / 8) + 255) / 256, 256>>>(x);
    k_w1T<<<(HID_C * IN_C + 255) / 256, 256>>>(w1);
    {
        dim3 grid(HID_C / BN, (N_NODES + BM - 1) / BM);
        k_gemm_f16<true><<<grid, 256>>>(xh, w1Th, nullptr, nullptr,
                                        h1h, h1h, N_NODES, IN_C, HID_C);
    }

    // join before aggregation
    cudaStreamWaitEvent(0, g_aux.ev_join, 0);

    // h = relu(Â h1 + b1)   (fp16 out)
    k_aggregate<<<N_NODES, 32>>>(h1h, b1, hh, 1);

    // g = Â h               (fp16 out, feeds GEMM2 A)
    k_aggregate<<<N_NODES, 32>>>(hh, nullptr, gh, 0);

    // [mu | logstd] = g @ wcat + [b_mu|b_ls]  (fp32 out, split halves)
    {
        dim3 grid((2 * OUT_C) / BN, (N_NODES + BM - 1) / BM);
        k_gemm_f16<false><<<grid, 256>>>(gh, wcatTh, b_mu, b_ls,
                                         out, out + (size_t)N_NODES * OUT_C,
                                         N_NODES, HID_C, OUT_C);
    }
}

// round 12
// speedup vs baseline: 3.1748x; 1.0821x over previous
#include <cuda_runtime.h>
#include <cuda_fp16.h>
#include <cstdint>
#include <cstddef>
#include <cstring>

#define N_NODES 50000
#define N_EDGES 500000
#define IN_C 512
#define HID_C 256
#define OUT_C 128

#define SCAN_B 1024
#define NB ((N_NODES + SCAN_B - 1) / SCAN_B)   // 49

// ---------------- scratch (device globals; no allocation) ----------------
__device__ int    g_degi[N_NODES];
__device__ int    g_cnt[N_NODES];
__device__ int    g_off[N_NODES + 1];
__device__ int    g_bsum[NB];
__device__ int2   g_csr[N_EDGES];             // (src, weight-as-bits fp32)
__device__ float  g_dis[N_NODES];
__device__ float  g_selfn[N_NODES];
__device__ __half g_xh  [(size_t)N_NODES * IN_C];   // x in fp16
__device__ __half g_h1h [(size_t)N_NODES * HID_C];  // GEMM1 out (fp16)
__device__ __half g_hh  [(size_t)N_NODES * HID_C];  // relu-agg out (fp16)
__device__ __half g_gh  [(size_t)N_NODES * HID_C];  // second agg out (fp16)
__device__ __half g_w1Th [HID_C * IN_C];            // [n][k] fp16
__device__ __half g_wcatTh[(2 * OUT_C) * HID_C];    // [n][k] fp16, [w_mu | w_ls]

// ---------------- bit-cast helpers ----------------
__device__ __forceinline__ uint32_t h2_as_u32(__half2 h) {
    uint32_t u; memcpy(&u, &h, 4); return u;
}
__device__ __forceinline__ __half2 u32_as_h2(uint32_t u) {
    __half2 h; memcpy(&h, &u, 4); return h;
}

// ---------------- streams/events (created pre-capture) ----------------
struct Aux {
    cudaStream_t s2;
    cudaEvent_t ev_fork, ev_join;
    Aux() {
        cudaStreamCreateWithFlags(&s2, cudaStreamNonBlocking);
        cudaEventCreateWithFlags(&ev_fork, cudaEventDisableTiming);
        cudaEventCreateWithFlags(&ev_join, cudaEventDisableTiming);
    }
};
static Aux g_aux;

// ---------------- CSR build ----------------
__global__ void k_zero() {
    int i = blockIdx.x * blockDim.x + threadIdx.x;
    if (i < N_NODES) { g_degi[i] = 0; g_cnt[i] = 0; }
}

__global__ void k_count(const int* __restrict__ dst) {
    int e = blockIdx.x * blockDim.x + threadIdx.x;
    if (e < N_EDGES) atomicAdd(&g_degi[dst[e]], 1);
}

__global__ void k_scan1() {
    __shared__ int sh[SCAN_B];
    int tid = threadIdx.x;
    int i = blockIdx.x * SCAN_B + tid;
    int v = (i < N_NODES) ? g_degi[i] : 0;
    if (i < N_NODES) {
        float degf = (float)v + 1.0f;
        g_dis[i]   = rsqrtf(degf);
        g_selfn[i] = 1.0f / degf;
    }
    sh[tid] = v;
    __syncthreads();
    for (int off = 1; off < SCAN_B; off <<= 1) {
        int t = (tid >= off) ? sh[tid - off] : 0;
        __syncthreads();
        sh[tid] += t;
        __syncthreads();
    }
    if (i < N_NODES) g_off[i + 1] = sh[tid];
    if (tid == SCAN_B - 1) g_bsum[blockIdx.x] = sh[tid];
}

__global__ void k_scan2() {
    int lane = threadIdx.x;
    int v0 = (lane < NB) ? g_bsum[lane] : 0;
    int v1 = (lane + 32 < NB) ? g_bsum[lane + 32] : 0;
    int s0 = v0;
    #pragma unroll
    for (int o = 1; o < 32; o <<= 1) {
        int t = __shfl_up_sync(0xffffffffu, s0, o);
        if (lane >= o) s0 += t;
    }
    int tot0 = __shfl_sync(0xffffffffu, s0, 31);
    int s1 = v1;
    #pragma unroll
    for (int o = 1; o < 32; o <<= 1) {
        int t = __shfl_up_sync(0xffffffffu, s1, o);
        if (lane >= o) s1 += t;
    }
    s1 += tot0;
    if (lane < NB)      g_bsum[lane]      = s0 - v0;
    if (lane + 32 < NB) g_bsum[lane + 32] = s1 - v1;
    if (lane == 0) g_off[0] = 0;
}

__global__ void k_scan3() {
    int tid = threadIdx.x;
    int i = blockIdx.x * SCAN_B + tid;
    if (i < N_NODES) g_off[i + 1] += g_bsum[blockIdx.x];
}

__global__ void k_fill(const int* __restrict__ src, const int* __restrict__ dst) {
    int e = blockIdx.x * blockDim.x + threadIdx.x;
    if (e < N_EDGES) {
        int d = dst[e];
        int s = src[e];
        int p = atomicAdd(&g_cnt[d], 1);
        int idx = g_off[d] + p;
        g_csr[idx] = make_int2(s, __float_as_int(g_dis[s]));
    }
}

// ---------------- fused conversions: x -> fp16 AND w1 -> [n][k] fp16 ----------------
#define XC8 ((int)((size_t)N_NODES * IN_C / 8))        // 3.2M chunks
#define W1C8 (HID_C * IN_C / 8)                         // 16384 chunks

__global__ void k_convert(const float* __restrict__ x, const float* __restrict__ w1) {
    int i = blockIdx.x * blockDim.x + threadIdx.x;
    if (i < XC8) {
        float4 a = ((const float4*)x)[(size_t)i * 2 + 0];
        float4 b = ((const float4*)x)[(size_t)i * 2 + 1];
        uint4 o;
        o.x = h2_as_u32(__floats2half2_rn(a.x, a.y));
        o.y = h2_as_u32(__floats2half2_rn(a.z, a.w));
        o.z = h2_as_u32(__floats2half2_rn(b.x, b.y));
        o.w = h2_as_u32(__floats2half2_rn(b.z, b.w));
        ((uint4*)g_xh)[i] = o;
    } else if (i < XC8 + W1C8) {
        int j = i - XC8;                    // 8 consecutive [n][k] outputs
        int n  = j / (IN_C / 8);
        int k0 = (j % (IN_C / 8)) * 8;
        __half o[8];
        #pragma unroll
        for (int q = 0; q < 8; q++)
            o[q] = __float2half_rn(w1[(size_t)(k0 + q) * HID_C + n]);
        *(uint4*)&g_w1Th[(size_t)n * IN_C + k0] = *(uint4*)o;
    }
}

__global__ void k_wcatT(const float* __restrict__ w_mu, const float* __restrict__ w_ls) {
    int i = blockIdx.x * blockDim.x + threadIdx.x;    // over 256*256
    if (i < (2 * OUT_C) * HID_C) {
        int n = i / HID_C;
        int k = i % HID_C;
        float v = (n < OUT_C) ? w_mu[(size_t)k * OUT_C + n]
                              : w_ls[(size_t)k * OUT_C + (n - OUT_C)];
        g_wcatTh[i] = __float2half_rn(v);
    }
}

// ---------------- fp16 tensor-core GEMM: ldmatrix + 3-stage cp.async ----------------
// BM=128 BN=128 BK=16(halves), 256 threads = 8 warps, warp tile 32x64 (2x8 m16n8k16)
#define BM 128
#define BN 128
#define BKH 16
#define SSH 24     // 48B row stride: 8-row ldmatrix addrs distinct mod 128B

__device__ __forceinline__ void cp16(uint32_t saddr, const void* g, int sz) {
    asm volatile("cp.async.ca.shared.global [%0], [%1], 16, %2;" :: "r"(saddr), "l"(g), "r"(sz));
}
__device__ __forceinline__ void cp_commit() { asm volatile("cp.async.commit_group;"); }
__device__ __forceinline__ void cp_wait0()  { asm volatile("cp.async.wait_group 0;"); }
__device__ __forceinline__ void cp_wait1()  { asm volatile("cp.async.wait_group 1;"); }

__device__ __forceinline__ void ldsm4(uint32_t& r0, uint32_t& r1, uint32_t& r2, uint32_t& r3,
                                      uint32_t addr) {
    asm volatile("ldmatrix.sync.aligned.m8n8.x4.shared.b16 {%0,%1,%2,%3}, [%4];"
                 : "=r"(r0), "=r"(r1), "=r"(r2), "=r"(r3) : "r"(addr));
}

template<bool HALF_OUT>
__global__ __launch_bounds__(256)
void k_gemm_f16(const __half* __restrict__ A, const __half* __restrict__ BT,
                const float* __restrict__ bias0, const float* __restrict__ bias1,
                void* __restrict__ out0v, void* __restrict__ out1v,
                int M, int K, int splitOut)
{
    __shared__ __half As[3][BM][SSH];
    __shared__ __half Bs[3][BN][SSH];

    const int tid  = threadIdx.x;
    const int lane = tid & 31;
    const int wid  = tid >> 5;

    const int row0 = blockIdx.y * BM;
    const int col0 = blockIdx.x * BN;

    const int wm0 = (wid & 3) * 32;
    const int wn0 = (wid >> 2) * 64;

    // ldmatrix lane-address decomposition (halves)
    const int lr  = lane & 7;
    const int sel = lane >> 3;                 // 0..3
    const int a_ro = ((sel & 1) << 3) + lr;
    const int a_co = (sel >> 1) << 3;
    const int b_ro = ((sel >> 1) << 3) + lr;
    const int b_co = (sel & 1) << 3;

    float acc[2][8][4];
    #pragma unroll
    for (int mi = 0; mi < 2; mi++)
        #pragma unroll
        for (int ni = 0; ni < 8; ni++)
            #pragma unroll
            for (int q = 0; q < 4; q++) acc[mi][ni][q] = 0.0f;

    // cp.async: 1 16B chunk per thread for A, 1 for B per tile
    const int t_r = tid >> 1;              // 0..127
    const int t_c = (tid & 1) * 8;         // 0 or 8 halves
    auto load_tile = [&](int s, int k0) {
        int gr = row0 + t_r;
        int ok = (gr < M) ? 16 : 0;
        int grc = (gr < M) ? gr : (M - 1);
        cp16((uint32_t)__cvta_generic_to_shared(&As[s][t_r][t_c]),
             &A[(size_t)grc * K + k0 + t_c], ok);
        cp16((uint32_t)__cvta_generic_to_shared(&Bs[s][t_r][t_c]),
             &BT[(size_t)(col0 + t_r) * K + k0 + t_c], 16);
    };

    const int nIter = K / BKH;
    load_tile(0, 0);
    cp_commit();
    if (nIter > 1) { load_tile(1, BKH); cp_commit(); }

    for (int it = 0; it < nIter; it++) {
        if (it + 1 < nIter) cp_wait1(); else cp_wait0();
        __syncthreads();

        const int buf = it % 3;
        uint32_t a[2][4];
        #pragma unroll
        for (int mi = 0; mi < 2; mi++) {
            uint32_t addr = (uint32_t)__cvta_generic_to_shared(
                &As[buf][wm0 + mi * 16 + a_ro][a_co]);
            ldsm4(a[mi][0], a[mi][1], a[mi][2], a[mi][3], addr);
        }
        #pragma unroll
        for (int np = 0; np < 4; np++) {
            uint32_t bb[4];
            uint32_t addr = (uint32_t)__cvta_generic_to_shared(
                &Bs[buf][wn0 + np * 16 + b_ro][b_co]);
            ldsm4(bb[0], bb[1], bb[2], bb[3], addr);
            #pragma unroll
            for (int par = 0; par < 2; par++) {
                int ni = np * 2 + par;
                uint32_t b0 = bb[par * 2 + 0];
                uint32_t b1 = bb[par * 2 + 1];
                #pragma unroll
                for (int mi = 0; mi < 2; mi++) {
                    asm volatile(
                        "mma.sync.aligned.m16n8k16.row.col.f32.f16.f16.f32 "
                        "{%0,%1,%2,%3}, {%4,%5,%6,%7}, {%8,%9}, {%0,%1,%2,%3};\n"
                        : "+f"(acc[mi][ni][0]), "+f"(acc[mi][ni][1]),
                          "+f"(acc[mi][ni][2]), "+f"(acc[mi][ni][3])
                        : "r"(a[mi][0]), "r"(a[mi][1]), "r"(a[mi][2]), "r"(a[mi][3]),
                          "r"(b0), "r"(b1));
                }
            }
        }

        if (it + 2 < nIter) {
            load_tile((it + 2) % 3, (it + 2) * BKH);
            cp_commit();
        }
    }

    // ---- epilogue: bias + split store ----
    const int lrow = lane >> 2;
    const int lcol = lane & 3;
    #pragma unroll
    for (int mi = 0; mi < 2; mi++) {
        #pragma unroll
        for (int half = 0; half < 2; half++) {
            int r = row0 + wm0 + mi * 16 + lrow + half * 8;
            if (r >= M) continue;
            #pragma unroll
            for (int ni = 0; ni < 8; ni++) {
                int c = col0 + wn0 + ni * 8 + lcol * 2;
                float v0 = acc[mi][ni][half * 2 + 0];
                float v1 = acc[mi][ni][half * 2 + 1];
                if (c < splitOut) {
                    if (bias0) { v0 += bias0[c]; v1 += bias0[c + 1]; }
                    if (HALF_OUT) {
                        *(__half2*)((__half*)out0v + (size_t)r * splitOut + c) =
                            __floats2half2_rn(v0, v1);
                    } else {
                        *(float2*)((float*)out0v + (size_t)r * splitOut + c) = make_float2(v0, v1);
                    }
                } else {
                    int cc = c - splitOut;
                    if (bias1) { v0 += bias1[cc]; v1 += bias1[cc + 1]; }
                    if (HALF_OUT) {
                        *(__half2*)((__half*)out1v + (size_t)r * splitOut + cc) =
                            __floats2half2_rn(v0, v1);
                    } else {
                        *(float2*)((float*)out1v + (size_t)r * splitOut + cc) = make_float2(v0, v1);
                    }
                }
            }
        }
    }
}

// ---------------- CSR aggregation (fp16 in/out, fp32 accumulate) ----------------
// 64 threads = 2 warps, each warp owns one node; thread owns 8 features.
__global__ void k_aggregate(const __half* __restrict__ hin,
                            const float* __restrict__ bias,
                            __half* __restrict__ hout,
                            int do_relu)
{
    int n = blockIdx.x * 2 + (threadIdx.x >> 5);
    if (n >= N_NODES) return;
    int t = threadIdx.x & 31;
    int fo = t * 8;

    float acc[8];
    #pragma unroll
    for (int j = 0; j < 8; j++) acc[j] = 0.0f;

    int beg = g_off[n], end = g_off[n + 1];

    auto accum = [&](int2 e) {
        float w = __int_as_float(e.y);
        uint4 v = *(const uint4*)&hin[(size_t)e.x * HID_C + fo];
        float2 f0 = __half22float2(u32_as_h2(v.x));
        float2 f1 = __half22float2(u32_as_h2(v.y));
        float2 f2 = __half22float2(u32_as_h2(v.z));
        float2 f3 = __half22float2(u32_as_h2(v.w));
        acc[0] = fmaf(w, f0.x, acc[0]); acc[1] = fmaf(w, f0.y, acc[1]);
        acc[2] = fmaf(w, f1.x, acc[2]); acc[3] = fmaf(w, f1.y, acc[3]);
        acc[4] = fmaf(w, f2.x, acc[4]); acc[5] = fmaf(w, f2.y, acc[5]);
        acc[6] = fmaf(w, f3.x, acc[6]); acc[7] = fmaf(w, f3.y, acc[7]);
    };

    int i = beg;
    for (; i + 4 <= end; i += 4) {
        int2 e0 = g_csr[i + 0];
        int2 e1 = g_csr[i + 1];
        int2 e2 = g_csr[i + 2];
        int2 e3 = g_csr[i + 3];
        accum(e0); accum(e1); accum(e2); accum(e3);
    }
    for (; i < end; i++) accum(g_csr[i]);

    float dn = g_dis[n];
    float sn = g_selfn[n];
    uint4 hv = *(const uint4*)&hin[(size_t)n * HID_C + fo];
    float2 s0 = __half22float2(u32_as_h2(hv.x));
    float2 s1 = __half22float2(u32_as_h2(hv.y));
    float2 s2 = __half22float2(u32_as_h2(hv.z));
    float2 s3 = __half22float2(u32_as_h2(hv.w));
    float sv[8] = {s0.x, s0.y, s1.x, s1.y, s2.x, s2.y, s3.x, s3.y};

    float r[8];
    #pragma unroll
    for (int j = 0; j < 8; j++) {
        float b = bias ? bias[fo + j] : 0.0f;
        r[j] = dn * acc[j] + sn * sv[j] + b;
        if (do_relu) r[j] = fmaxf(r[j], 0.0f);
    }
    uint4 o;
    o.x = h2_as_u32(__floats2half2_rn(r[0], r[1]));
    o.y = h2_as_u32(__floats2half2_rn(r[2], r[3]));
    o.z = h2_as_u32(__floats2half2_rn(r[4], r[5]));
    o.w = h2_as_u32(__floats2half2_rn(r[6], r[7]));
    *(uint4*)&hout[(size_t)n * HID_C + fo] = o;
}

// ---------------- launch ----------------
extern "C" void kernel_launch(void* const* d_in, const int* in_sizes, int n_in,
                              void* d_out, int out_size)
{
    const float* x    = (const float*)d_in[0];
    const int*   ei   = (const int*)  d_in[1];
    const float* w1   = (const float*)d_in[2];
    const float* b1   = (const float*)d_in[3];
    const float* w_mu = (const float*)d_in[4];
    const float* b_mu = (const float*)d_in[5];
    const float* w_ls = (const float*)d_in[6];
    const float* b_ls = (const float*)d_in[7];
    float* out = (float*)d_out;

    const int* src = ei;
    const int* dst = ei + N_EDGES;

    void *p_xh, *p_h1h, *p_hh, *p_gh, *p_w1Th, *p_wcatTh;
    cudaGetSymbolAddress(&p_xh,     g_xh);
    cudaGetSymbolAddress(&p_h1h,    g_h1h);
    cudaGetSymbolAddress(&p_hh,     g_hh);
    cudaGetSymbolAddress(&p_gh,     g_gh);
    cudaGetSymbolAddress(&p_w1Th,   g_w1Th);
    cudaGetSymbolAddress(&p_wcatTh, g_wcatTh);
    __half* xh     = (__half*)p_xh;
    __half* h1h    = (__half*)p_h1h;
    __half* hh     = (__half*)p_hh;
    __half* gh     = (__half*)p_gh;
    __half* w1Th   = (__half*)p_w1Th;
    __half* wcatTh = (__half*)p_wcatTh;

    // fork: CSR build + wcatT on side stream
    cudaEventRecord(g_aux.ev_fork, 0);
    cudaStreamWaitEvent(g_aux.s2, g_aux.ev_fork, 0);

    k_zero <<<(N_NODES + 255) / 256, 256, 0, g_aux.s2>>>();
    k_count<<<(N_EDGES + 255) / 256, 256, 0, g_aux.s2>>>(dst);
    k_scan1<<<NB, SCAN_B, 0, g_aux.s2>>>();
    k_scan2<<<1, 32, 0, g_aux.s2>>>();
    k_scan3<<<NB, SCAN_B, 0, g_aux.s2>>>();
    k_fill <<<(N_EDGES + 255) / 256, 256, 0, g_aux.s2>>>(src, dst);
    k_wcatT<<<((2 * OUT_C) * HID_C + 255) / 256, 256, 0, g_aux.s2>>>(w_mu, w_ls);
    cudaEventRecord(g_aux.ev_join, g_aux.s2);

    // main stream: fused x+w1 conversion, then GEMM1 (overlaps CSR build)
    k_convert<<<(XC8 + W1C8 + 255) / 256, 256>>>(x, w1);
    {
        dim3 grid(HID_C / BN, (N_NODES + BM - 1) / BM);
        k_gemm_f16<true><<<grid, 256>>>(xh, w1Th, nullptr, nullptr,
                                        h1h, h1h, N_NODES, IN_C, HID_C);
    }

    // join before aggregation
    cudaStreamWaitEvent(0, g_aux.ev_join, 0);

    // h = relu(Â h1 + b1)   (fp16 out)
    k_aggregate<<<(N_NODES + 1) / 2, 64>>>(h1h, b1, hh, 1);

    // g = Â h               (fp16 out, feeds GEMM2 A)
    k_aggregate<<<(N_NODES + 1) / 2, 64>>>(hh, nullptr, gh, 0);

    // [mu | logstd] = g @ wcat + [b_mu|b_ls]  (fp32 out, split halves)
    {
        dim3 grid((2 * OUT_C) / BN, (N_NODES + BM - 1) / BM);
        k_gemm_f16<false><<<grid, 256>>>(gh, wcatTh, b_mu, b_ls,
                                         out, out + (size_t)N_NODES * OUT_C,
                                         N_NODES, HID_C, OUT_C);
    }
}

// round 14
// speedup vs baseline: 3.3328x; 1.0498x over previous
#include <cuda_runtime.h>
#include <cuda_fp16.h>
#include <cstdint>
#include <cstddef>
#include <cstring>

#define N_NODES 50000
#define N_EDGES 500000
#define IN_C 512
#define HID_C 256
#define OUT_C 128

#define SCAN_B 1024
#define NB ((N_NODES + SCAN_B - 1) / SCAN_B)   // 49

// ---------------- scratch (device globals; no allocation) ----------------
__device__ int    g_degi[N_NODES];
__device__ int    g_cnt[N_NODES];
__device__ int    g_off[N_NODES + 1];
__device__ int    g_bsum[NB];
__device__ int2   g_csr[N_EDGES];             // (src, weight-as-bits fp32)
__device__ float  g_dis[N_NODES];
__device__ float  g_selfn[N_NODES];
__device__ __half g_h1h [(size_t)N_NODES * HID_C];  // GEMM1 out (fp16)
__device__ __half g_hh  [(size_t)N_NODES * HID_C];  // relu-agg out (fp16)
__device__ __half g_gh  [(size_t)N_NODES * HID_C];  // second agg out (fp16)
__device__ __half g_w1Th [HID_C * IN_C];            // [n][k] fp16
__device__ __half g_wcatTh[(2 * OUT_C) * HID_C];    // [n][k] fp16, [w_mu | w_ls]

// ---------------- bit-cast helpers ----------------
__device__ __forceinline__ uint32_t h2_as_u32(__half2 h) {
    uint32_t u; memcpy(&u, &h, 4); return u;
}
__device__ __forceinline__ __half2 u32_as_h2(uint32_t u) {
    __half2 h; memcpy(&h, &u, 4); return h;
}

// ---------------- streams/events (created pre-capture) ----------------
struct Aux {
    cudaStream_t s2;
    cudaEvent_t ev_fork, ev_w1, ev_join;
    Aux() {
        cudaStreamCreateWithFlags(&s2, cudaStreamNonBlocking);
        cudaEventCreateWithFlags(&ev_fork, cudaEventDisableTiming);
        cudaEventCreateWithFlags(&ev_w1,   cudaEventDisableTiming);
        cudaEventCreateWithFlags(&ev_join, cudaEventDisableTiming);
    }
};
static Aux g_aux;

// ---------------- CSR build ----------------
__global__ void k_zero() {
    int i = blockIdx.x * blockDim.x + threadIdx.x;
    if (i < N_NODES) { g_degi[i] = 0; g_cnt[i] = 0; }
}

__global__ void k_count(const int* __restrict__ dst) {
    int e = blockIdx.x * blockDim.x + threadIdx.x;
    if (e < N_EDGES) atomicAdd(&g_degi[dst[e]], 1);
}

__global__ void k_scan1() {
    __shared__ int sh[SCAN_B];
    int tid = threadIdx.x;
    int i = blockIdx.x * SCAN_B + tid;
    int v = (i < N_NODES) ? g_degi[i] : 0;
    if (i < N_NODES) {
        float degf = (float)v + 1.0f;
        g_dis[i]   = rsqrtf(degf);
        g_selfn[i] = 1.0f / degf;
    }
    sh[tid] = v;
    __syncthreads();
    for (int off = 1; off < SCAN_B; off <<= 1) {
        int t = (tid >= off) ? sh[tid - off] : 0;
        __syncthreads();
        sh[tid] += t;
        __syncthreads();
    }
    if (i < N_NODES) g_off[i + 1] = sh[tid];
    if (tid == SCAN_B - 1) g_bsum[blockIdx.x] = sh[tid];
}

__global__ void k_scan2() {
    int lane = threadIdx.x;
    int v0 = (lane < NB) ? g_bsum[lane] : 0;
    int v1 = (lane + 32 < NB) ? g_bsum[lane + 32] : 0;
    int s0 = v0;
    #pragma unroll
    for (int o = 1; o < 32; o <<= 1) {
        int t = __shfl_up_sync(0xffffffffu, s0, o);
        if (lane >= o) s0 += t;
    }
    int tot0 = __shfl_sync(0xffffffffu, s0, 31);
    int s1 = v1;
    #pragma unroll
    for (int o = 1; o < 32; o <<= 1) {
        int t = __shfl_up_sync(0xffffffffu, s1, o);
        if (lane >= o) s1 += t;
    }
    s1 += tot0;
    if (lane < NB)      g_bsum[lane]      = s0 - v0;
    if (lane + 32 < NB) g_bsum[lane + 32] = s1 - v1;
    if (lane == 0) g_off[0] = 0;
}

__global__ void k_scan3() {
    int tid = threadIdx.x;
    int i = blockIdx.x * SCAN_B + tid;
    if (i < N_NODES) g_off[i + 1] += g_bsum[blockIdx.x];
}

__global__ void k_fill(const int* __restrict__ src, const int* __restrict__ dst) {
    int e = blockIdx.x * blockDim.x + threadIdx.x;
    if (e < N_EDGES) {
        int d = dst[e];
        int s = src[e];
        int p = atomicAdd(&g_cnt[d], 1);
        int idx = g_off[d] + p;
        g_csr[idx] = make_int2(s, __float_as_int(g_dis[s]));
    }
}

// ---------------- weight transposes [n][k] fp16 ----------------
__global__ void k_w1T(const float* __restrict__ w1) {
    int j = blockIdx.x * blockDim.x + threadIdx.x;    // over HID_C*IN_C/8
    if (j < HID_C * IN_C / 8) {
        int n  = j / (IN_C / 8);
        int k0 = (j % (IN_C / 8)) * 8;
        __half o[8];
        #pragma unroll
        for (int q = 0; q < 8; q++)
            o[q] = __float2half_rn(w1[(size_t)(k0 + q) * HID_C + n]);
        *(uint4*)&g_w1Th[(size_t)n * IN_C + k0] = *(uint4*)o;
    }
}

__global__ void k_wcatT(const float* __restrict__ w_mu, const float* __restrict__ w_ls) {
    int i = blockIdx.x * blockDim.x + threadIdx.x;    // over 256*256
    if (i < (2 * OUT_C) * HID_C) {
        int n = i / HID_C;
        int k = i % HID_C;
        float v = (n < OUT_C) ? w_mu[(size_t)k * OUT_C + n]
                              : w_ls[(size_t)k * OUT_C + (n - OUT_C)];
        g_wcatTh[i] = __float2half_rn(v);
    }
}

// ---------------- fp16 tensor-core GEMM: ldmatrix + pipelined loads ----------------
// BM=128 BN=128 BK=16(halves), 256 threads = 8 warps, warp tile 32x64 (2x8 m16n8k16)
// A_F32: A is fp32 in gmem, converted in-register before STS (fuses x->fp16).
#define BM 128
#define BN 128
#define BKH 16
#define SSH 24     // 48B row stride: 8-row ldmatrix addrs distinct mod 128B

__device__ __forceinline__ void cp16(uint32_t saddr, const void* g, int sz) {
    asm volatile("cp.async.ca.shared.global [%0], [%1], 16, %2;" :: "r"(saddr), "l"(g), "r"(sz));
}
__device__ __forceinline__ void cp_commit() { asm volatile("cp.async.commit_group;"); }
__device__ __forceinline__ void cp_wait0()  { asm volatile("cp.async.wait_group 0;"); }
__device__ __forceinline__ void cp_wait1()  { asm volatile("cp.async.wait_group 1;"); }

__device__ __forceinline__ void ldsm4(uint32_t& r0, uint32_t& r1, uint32_t& r2, uint32_t& r3,
                                      uint32_t addr) {
    asm volatile("ldmatrix.sync.aligned.m8n8.x4.shared.b16 {%0,%1,%2,%3}, [%4];"
                 : "=r"(r0), "=r"(r1), "=r"(r2), "=r"(r3) : "r"(addr));
}

template<bool A_F32, bool HALF_OUT>
__global__ __launch_bounds__(256)
void k_gemm_f16(const void* __restrict__ Aptr, const __half* __restrict__ BT,
                const float* __restrict__ bias0, const float* __restrict__ bias1,
                void* __restrict__ out0v, void* __restrict__ out1v,
                int M, int K, int splitOut)
{
    __shared__ __half As[3][BM][SSH];
    __shared__ __half Bs[3][BN][SSH];

    const __half* Ah = (const __half*)Aptr;
    const float*  Af = (const float*)Aptr;

    const int tid  = threadIdx.x;
    const int lane = tid & 31;
    const int wid  = tid >> 5;

    const int row0 = blockIdx.y * BM;
    const int col0 = blockIdx.x * BN;

    const int wm0 = (wid & 3) * 32;
    const int wn0 = (wid >> 2) * 64;

    // ldmatrix lane-address decomposition (halves)
    const int lr  = lane & 7;
    const int sel = lane >> 3;                 // 0..3
    const int a_ro = ((sel & 1) << 3) + lr;
    const int a_co = (sel >> 1) << 3;
    const int b_ro = ((sel >> 1) << 3) + lr;
    const int b_co = (sel & 1) << 3;

    float acc[2][8][4];
    #pragma unroll
    for (int mi = 0; mi < 2; mi++)
        #pragma unroll
        for (int ni = 0; ni < 8; ni++)
            #pragma unroll
            for (int q = 0; q < 4; q++) acc[mi][ni][q] = 0.0f;

    // per-thread load coords: 1 16B fp16 chunk (= 8 halves) for A and B each
    const int t_r = tid >> 1;              // 0..127
    const int t_c = (tid & 1) * 8;         // 0 or 8 (element offset)
    const int a_row_clamped = (row0 + t_r < M) ? (row0 + t_r) : (M - 1);
    const bool a_valid = (row0 + t_r < M);

    float4 ar0, ar1;                        // fp32 A staging (A_F32 path)
    auto ldgA = [&](int k0) {
        const float* p = &Af[(size_t)a_row_clamped * K + k0 + t_c];
        ar0 = *(const float4*)p;
        ar1 = *(const float4*)(p + 4);
    };
    auto stsA = [&](int s) {
        uint4 o;
        o.x = h2_as_u32(__floats2half2_rn(ar0.x, ar0.y));
        o.y = h2_as_u32(__floats2half2_rn(ar0.z, ar0.w));
        o.z = h2_as_u32(__floats2half2_rn(ar1.x, ar1.y));
        o.w = h2_as_u32(__floats2half2_rn(ar1.z, ar1.w));
        *(uint4*)&As[s][t_r][t_c] = o;
    };
    auto cpA16 = [&](int s, int k0) {
        cp16((uint32_t)__cvta_generic_to_shared(&As[s][t_r][t_c]),
             &Ah[(size_t)a_row_clamped * K + k0 + t_c], 16);
    };
    auto cpB = [&](int s, int k0) {
        cp16((uint32_t)__cvta_generic_to_shared(&Bs[s][t_r][t_c]),
             &BT[(size_t)(col0 + t_r) * K + k0 + t_c], 16);
    };

    const int nIter = K / BKH;

    // ---- prologue: tiles 0 and 1 ----
    if (A_F32) {
        ldgA(0);       stsA(0);
        if (nIter > 1) { ldgA(BKH); stsA(1); }
        cpB(0, 0); cp_commit();
        if (nIter > 1) { cpB(1, BKH); cp_commit(); }
    } else {
        cpA16(0, 0); cpB(0, 0); cp_commit();
        if (nIter > 1) { cpA16(1, BKH); cpB(1, BKH); cp_commit(); }
    }

    for (int it = 0; it < nIter; it++) {
        if (it + 1 < nIter) cp_wait1(); else cp_wait0();
        __syncthreads();

        // issue next-next A global loads early (latency hidden under mma)
        if (A_F32 && it + 2 < nIter) ldgA((it + 2) * BKH);

        const int buf = it % 3;
        uint32_t a[2][4];
        #pragma unroll
        for (int mi = 0; mi < 2; mi++) {
            uint32_t addr = (uint32_t)__cvta_generic_to_shared(
                &As[buf][wm0 + mi * 16 + a_ro][a_co]);
            ldsm4(a[mi][0], a[mi][1], a[mi][2], a[mi][3], addr);
        }
        #pragma unroll
        for (int np = 0; np < 4; np++) {
            uint32_t bb[4];
            uint32_t addr = (uint32_t)__cvta_generic_to_shared(
                &Bs[buf][wn0 + np * 16 + b_ro][b_co]);
            ldsm4(bb[0], bb[1], bb[2], bb[3], addr);
            #pragma unroll
            for (int par = 0; par < 2; par++) {
                int ni = np * 2 + par;
                uint32_t b0 = bb[par * 2 + 0];
                uint32_t b1 = bb[par * 2 + 1];
                #pragma unroll
                for (int mi = 0; mi < 2; mi++) {
                    asm volatile(
                        "mma.sync.aligned.m16n8k16.row.col.f32.f16.f16.f32 "
                        "{%0,%1,%2,%3}, {%4,%5,%6,%7}, {%8,%9}, {%0,%1,%2,%3};\n"
                        : "+f"(acc[mi][ni][0]), "+f"(acc[mi][ni][1]),
                          "+f"(acc[mi][ni][2]), "+f"(acc[mi][ni][3])
                        : "r"(a[mi][0]), "r"(a[mi][1]), "r"(a[mi][2]), "r"(a[mi][3]),
                          "r"(b0), "r"(b1));
                }
            }
        }

        if (it + 2 < nIter) {
            int nb = (it + 2) % 3;
            if (A_F32) {
                stsA(nb);
                cpB(nb, (it + 2) * BKH);
            } else {
                cpA16(nb, (it + 2) * BKH);
                cpB(nb, (it + 2) * BKH);
            }
            cp_commit();
        }
    }

    // ---- epilogue: bias + split store ----
    const int lrow = lane >> 2;
    const int lcol = lane & 3;
    #pragma unroll
    for (int mi = 0; mi < 2; mi++) {
        #pragma unroll
        for (int half = 0; half < 2; half++) {
            int r = row0 + wm0 + mi * 16 + lrow + half * 8;
            if (r >= M) continue;
            #pragma unroll
            for (int ni = 0; ni < 8; ni++) {
                int c = col0 + wn0 + ni * 8 + lcol * 2;
                float v0 = acc[mi][ni][half * 2 + 0];
                float v1 = acc[mi][ni][half * 2 + 1];
                if (c < splitOut) {
                    if (bias0) { v0 += bias0[c]; v1 += bias0[c + 1]; }
                    if (HALF_OUT) {
                        *(__half2*)((__half*)out0v + (size_t)r * splitOut + c) =
                            __floats2half2_rn(v0, v1);
                    } else {
                        *(float2*)((float*)out0v + (size_t)r * splitOut + c) = make_float2(v0, v1);
                    }
                } else {
                    int cc = c - splitOut;
                    if (bias1) { v0 += bias1[cc]; v1 += bias1[cc + 1]; }
                    if (HALF_OUT) {
                        *(__half2*)((__half*)out1v + (size_t)r * splitOut + cc) =
                            __floats2half2_rn(v0, v1);
                    } else {
                        *(float2*)((float*)out1v + (size_t)r * splitOut + cc) = make_float2(v0, v1);
                    }
                }
            }
        }
    }
}

// ---------------- CSR aggregation (fp16 in/out, fp32 accumulate) ----------------
// 64 threads = 2 warps, each warp owns one node; thread owns 8 features.
__global__ void k_aggregate(const __half* __restrict__ hin,
                            const float* __restrict__ bias,
                            __half* __restrict__ hout,
                            int do_relu)
{
    int n = blockIdx.x * 2 + (threadIdx.x >> 5);
    if (n >= N_NODES) return;
    int t = threadIdx.x & 31;
    int fo = t * 8;

    float acc[8];
    #pragma unroll
    for (int j = 0; j < 8; j++) acc[j] = 0.0f;

    int beg = g_off[n], end = g_off[n + 1];

    auto accum = [&](int2 e) {
        float w = __int_as_float(e.y);
        uint4 v = *(const uint4*)&hin[(size_t)e.x * HID_C + fo];
        float2 f0 = __half22float2(u32_as_h2(v.x));
        float2 f1 = __half22float2(u32_as_h2(v.y));
        float2 f2 = __half22float2(u32_as_h2(v.z));
        float2 f3 = __half22float2(u32_as_h2(v.w));
        acc[0] = fmaf(w, f0.x, acc[0]); acc[1] = fmaf(w, f0.y, acc[1]);
        acc[2] = fmaf(w, f1.x, acc[2]); acc[3] = fmaf(w, f1.y, acc[3]);
        acc[4] = fmaf(w, f2.x, acc[4]); acc[5] = fmaf(w, f2.y, acc[5]);
        acc[6] = fmaf(w, f3.x, acc[6]); acc[7] = fmaf(w, f3.y, acc[7]);
    };

    int i = beg;
    for (; i + 4 <= end; i += 4) {
        int2 e0 = g_csr[i + 0];
        int2 e1 = g_csr[i + 1];
        int2 e2 = g_csr[i + 2];
        int2 e3 = g_csr[i + 3];
        accum(e0); accum(e1); accum(e2); accum(e3);
    }
    for (; i < end; i++) accum(g_csr[i]);

    float dn = g_dis[n];
    float sn = g_selfn[n];
    uint4 hv = *(const uint4*)&hin[(size_t)n * HID_C + fo];
    float2 s0 = __half22float2(u32_as_h2(hv.x));
    float2 s1 = __half22float2(u32_as_h2(hv.y));
    float2 s2 = __half22float2(u32_as_h2(hv.z));
    float2 s3 = __half22float2(u32_as_h2(hv.w));
    float sv[8] = {s0.x, s0.y, s1.x, s1.y, s2.x, s2.y, s3.x, s3.y};

    float r[8];
    #pragma unroll
    for (int j = 0; j < 8; j++) {
        float b = bias ? bias[fo + j] : 0.0f;
        r[j] = dn * acc[j] + sn * sv[j] + b;
        if (do_relu) r[j] = fmaxf(r[j], 0.0f);
    }
    uint4 o;
    o.x = h2_as_u32(__floats2half2_rn(r[0], r[1]));
    o.y = h2_as_u32(__floats2half2_rn(r[2], r[3]));
    o.z = h2_as_u32(__floats2half2_rn(r[4], r[5]));
    o.w = h2_as_u32(__floats2half2_rn(r[6], r[7]));
    *(uint4*)&hout[(size_t)n * HID_C + fo] = o;
}

// ---------------- launch ----------------
extern "C" void kernel_launch(void* const* d_in, const int* in_sizes, int n_in,
                              void* d_out, int out_size)
{
    const float* x    = (const float*)d_in[0];
    const int*   ei   = (const int*)  d_in[1];
    const float* w1   = (const float*)d_in[2];
    const float* b1   = (const float*)d_in[3];
    const float* w_mu = (const float*)d_in[4];
    const float* b_mu = (const float*)d_in[5];
    const float* w_ls = (const float*)d_in[6];
    const float* b_ls = (const float*)d_in[7];
    float* out = (float*)d_out;

    const int* src = ei;
    const int* dst = ei + N_EDGES;

    void *p_h1h, *p_hh, *p_gh, *p_w1Th, *p_wcatTh;
    cudaGetSymbolAddress(&p_h1h,    g_h1h);
    cudaGetSymbolAddress(&p_hh,     g_hh);
    cudaGetSymbolAddress(&p_gh,     g_gh);
    cudaGetSymbolAddress(&p_w1Th,   g_w1Th);
    cudaGetSymbolAddress(&p_wcatTh, g_wcatTh);
    __half* h1h    = (__half*)p_h1h;
    __half* hh     = (__half*)p_hh;
    __half* gh     = (__half*)p_gh;
    __half* w1Th   = (__half*)p_w1Th;
    __half* wcatTh = (__half*)p_wcatTh;

    // fork: w1T first (GEMM1 dependency), then CSR build + wcatT on side stream
    cudaEventRecord(g_aux.ev_fork, 0);
    cudaStreamWaitEvent(g_aux.s2, g_aux.ev_fork, 0);

    k_w1T<<<(HID_C * IN_C / 8 + 255) / 256, 256, 0, g_aux.s2>>>(w1);
    cudaEventRecord(g_aux.ev_w1, g_aux.s2);

    k_zero <<<(N_NODES + 255) / 256, 256, 0, g_aux.s2>>>();
    k_count<<<(N_EDGES + 255) / 256, 256, 0, g_aux.s2>>>(dst);
    k_scan1<<<NB, SCAN_B, 0, g_aux.s2>>>();
    k_scan2<<<1, 32, 0, g_aux.s2>>>();
    k_scan3<<<NB, SCAN_B, 0, g_aux.s2>>>();
    k_fill <<<(N_EDGES + 255) / 256, 256, 0, g_aux.s2>>>(src, dst);
    k_wcatT<<<((2 * OUT_C) * HID_C + 255) / 256, 256, 0, g_aux.s2>>>(w_mu, w_ls);
    cudaEventRecord(g_aux.ev_join, g_aux.s2);

    // main stream: GEMM1 directly on fp32 x (in-kernel conversion), overlaps CSR build
    cudaStreamWaitEvent(0, g_aux.ev_w1, 0);
    {
        dim3 grid(HID_C / BN, (N_NODES + BM - 1) / BM);
        k_gemm_f16<true, true><<<grid, 256>>>(x, w1Th, nullptr, nullptr,
                                              h1h, h1h, N_NODES, IN_C, HID_C);
    }

    // join before aggregation
    cudaStreamWaitEvent(0, g_aux.ev_join, 0);

    // h = relu(Â h1 + b1)   (fp16 out)
    k_aggregate<<<(N_NODES + 1) / 2, 64>>>(h1h, b1, hh, 1);

    // g = Â h               (fp16 out, feeds GEMM2 A)
    k_aggregate<<<(N_NODES + 1) / 2, 64>>>(hh, nullptr, gh, 0);

    // [mu | logstd] = g @ wcat + [b_mu|b_ls]  (fp32 out, split halves)
    {
        dim3 grid((2 * OUT_C) / BN, (N_NODES + BM - 1) / BM);
        k_gemm_f16<false, false><<<grid, 256>>>(gh, wcatTh, b_mu, b_ls,
                                                out, out + (size_t)N_NODES * OUT_C,
                                                N_NODES, HID_C, OUT_C);
    }
}